// round 1
// baseline (speedup 1.0000x reference)
#include <cuda_runtime.h>
#include <math.h>

// Problem constants (fixed by the dataset)
#define NN   20000   // nodes
#define KK   16      // neighbors per direction
#define DD   256     // embed dim
#define VV   64      // edge vocab
#define KDIM 320     // GEMM K = D (node part) + V (edge-count part)

// ---------------- scratch (static device globals; no allocation) -------------
__device__ float g_S[NN * KDIM];          // [N,320]: cols 0..255 = node agg, 256..319 = C
__device__ float g_WB[3][KDIM * DD];      // per layer: rows 0..255 = W_top, 256..319 = E@W_bot
__device__ float g_partials[1024];        // per-block kld partial sums (written every call)

// ---------------- 1) build combined weights WB_l ------------------------------
// grid: (320, 3), block: 256
__global__ void prep_wb(const float* __restrict__ W1, const float* __restrict__ E1,
                        const float* __restrict__ W2, const float* __restrict__ E2,
                        const float* __restrict__ W3, const float* __restrict__ E3)
{
    const int r = blockIdx.x;          // 0..319
    const int l = blockIdx.y;          // 0..2
    const int d = threadIdx.x;         // 0..255
    const float* W = (l == 0) ? W1 : (l == 1) ? W2 : W3;
    const float* E = (l == 0) ? E1 : (l == 1) ? E2 : E3;
    float* WB = g_WB[l];

    if (r < DD) {
        WB[r * DD + d] = W[r * DD + d];          // W_top rows
    } else {
        const int v = r - DD;
        __shared__ float sE[DD];
        sE[d] = E[v * DD + d];
        __syncthreads();
        float acc = 0.f;
        #pragma unroll 8
        for (int j = 0; j < DD; j++)
            acc += sE[j] * W[(DD + j) * DD + d]; // E[v,:] @ W_bot
        WB[r * DD + d] = acc;
    }
}

// ---------------- 2) per-node edge-vocab mask histogram C[n,v] ---------------
// one warp per node; lane owns vocab slots (lane, lane+32). grid: N/8, block 256.
__global__ void compute_c(const int* __restrict__ ie, const float* __restrict__ im,
                          const int* __restrict__ oe, const float* __restrict__ om)
{
    const int warp = threadIdx.x >> 5;
    const int lane = threadIdx.x & 31;
    const int n = blockIdx.x * 8 + warp;
    if (n >= NN) return;

    int   e;
    float m;
    if (lane < KK) { e = ie[n * KK + lane];        m = im[n * KK + lane]; }
    else           { e = oe[n * KK + lane - KK];   m = om[n * KK + lane - KK]; }

    float c0 = 0.f, c1 = 0.f;
    #pragma unroll
    for (int s = 0; s < 32; s++) {
        const int   ev = __shfl_sync(0xFFFFFFFFu, e, s);
        const float mv = __shfl_sync(0xFFFFFFFFu, m, s);
        if (ev == lane)      c0 += mv;
        if (ev == lane + 32) c1 += mv;
    }
    g_S[n * KDIM + DD + lane]      = c0;
    g_S[n * KDIM + DD + 32 + lane] = c1;
}

// ---------------- 3) masked neighbor gather-sum into g_S[:,0:256] ------------
// 64 threads per node (float4 over 256 cols), 4 nodes per block. grid: N/4.
__global__ void gather_sum(const float* __restrict__ src,
                           const int*   __restrict__ ii, const float* __restrict__ imk,
                           const int*   __restrict__ oi, const float* __restrict__ omk)
{
    const int n  = blockIdx.x * 4 + (threadIdx.x >> 6);
    const int c4 = (threadIdx.x & 63) * 4;
    if (n >= NN) return;

    float4 acc = make_float4(0.f, 0.f, 0.f, 0.f);
    #pragma unroll
    for (int k = 0; k < KK; k++) {
        const int   idx = ii[n * KK + k];
        const float m   = imk[n * KK + k];
        const float4 v  = *(const float4*)(src + (size_t)idx * DD + c4);
        acc.x += m * v.x; acc.y += m * v.y; acc.z += m * v.z; acc.w += m * v.w;
    }
    #pragma unroll
    for (int k = 0; k < KK; k++) {
        const int   idx = oi[n * KK + k];
        const float m   = omk[n * KK + k];
        const float4 v  = *(const float4*)(src + (size_t)idx * DD + c4);
        acc.x += m * v.x; acc.y += m * v.y; acc.z += m * v.z; acc.w += m * v.w;
    }
    *(float4*)(g_S + (size_t)n * KDIM + c4) = acc;
}

// ---------------- 4) GEMM [N,320]x[320,256] + fused epilogue -----------------
// MODE 0: out = base + acc + 2*bias            (hidden)
// MODE 1: kld partial += -tanh(x)^2            (mu branch, no store)
// MODE 2: kld partial += 1 + 2t - exp(2t)      (logvar branch, no store)
#define BM 128
#define BN 128
#define BK 16

template <int MODE>
__global__ __launch_bounds__(256, 2)
void gemm_ep(const float* __restrict__ B,       // g_WB[l]
             const float* __restrict__ base,
             const float* __restrict__ bias,
             float* __restrict__ out,            // only MODE 0
             int poff)                           // only MODE 1/2
{
    __shared__ float As[BK][BM];
    __shared__ float Bs[BK][BN];

    const float* A = g_S;
    const int tid = threadIdx.x;
    const int m0 = blockIdx.x * BM;
    const int n0 = blockIdx.y * BN;
    const int ty = tid >> 4, tx = tid & 15;

    const int arow = tid >> 2,  acol = (tid & 3) * 4;
    const int brow = tid >> 5,  bcol = (tid & 31) * 4;

    float acc[8][8];
    #pragma unroll
    for (int i = 0; i < 8; i++)
        #pragma unroll
        for (int j = 0; j < 8; j++) acc[i][j] = 0.f;

    for (int k0 = 0; k0 < KDIM; k0 += BK) {
        #pragma unroll
        for (int h = 0; h < 2; h++) {
            const int r = m0 + arow + h * 64;
            float4 v = make_float4(0.f, 0.f, 0.f, 0.f);
            if (r < NN) v = *(const float4*)(A + (size_t)r * KDIM + k0 + acol);
            As[acol + 0][arow + h * 64] = v.x;
            As[acol + 1][arow + h * 64] = v.y;
            As[acol + 2][arow + h * 64] = v.z;
            As[acol + 3][arow + h * 64] = v.w;
        }
        #pragma unroll
        for (int h = 0; h < 2; h++) {
            const float4 v = *(const float4*)(B + (size_t)(k0 + brow + h * 8) * DD + n0 + bcol);
            *(float4*)&Bs[brow + h * 8][bcol] = v;
        }
        __syncthreads();

        #pragma unroll
        for (int kk = 0; kk < BK; kk++) {
            float a[8], b[8];
            #pragma unroll
            for (int i = 0; i < 8; i++) a[i] = As[kk][ty * 8 + i];
            #pragma unroll
            for (int j = 0; j < 8; j++) b[j] = Bs[kk][tx * 8 + j];
            #pragma unroll
            for (int i = 0; i < 8; i++)
                #pragma unroll
                for (int j = 0; j < 8; j++) acc[i][j] += a[i] * b[j];
        }
        __syncthreads();
    }

    if (MODE == 0) {
        #pragma unroll
        for (int i = 0; i < 8; i++) {
            const int r = m0 + ty * 8 + i;
            if (r >= NN) continue;
            #pragma unroll
            for (int j = 0; j < 8; j++) {
                const int c = n0 + tx * 8 + j;
                out[(size_t)r * DD + c] = base[(size_t)r * DD + c] + acc[i][j] + 2.f * bias[c];
            }
        }
    } else {
        float s = 0.f;
        #pragma unroll
        for (int i = 0; i < 8; i++) {
            const int r = m0 + ty * 8 + i;
            if (r >= NN) continue;
            #pragma unroll
            for (int j = 0; j < 8; j++) {
                const int c = n0 + tx * 8 + j;
                const float x = base[(size_t)r * DD + c] + acc[i][j] + 2.f * bias[c];
                const float t = tanhf(x);
                if (MODE == 1) s -= t * t;
                else           s += 1.f + 2.f * t - expf(2.f * t);
            }
        }
        __shared__ float red[256];
        red[tid] = s;
        __syncthreads();
        #pragma unroll
        for (int o = 128; o > 0; o >>= 1) {
            if (tid < o) red[tid] += red[tid + o];
            __syncthreads();
        }
        if (tid == 0)
            g_partials[poff + blockIdx.y * gridDim.x + blockIdx.x] = red[0];
    }
}

// ---------------- 5) deterministic final kld reduction -----------------------
__global__ void kld_final(int nslots, float* __restrict__ out_kld)
{
    if (threadIdx.x == 0 && blockIdx.x == 0) {
        double s = 0.0;
        for (int i = 0; i < nslots; i++) s += (double)g_partials[i];
        out_kld[0] = (float)(-0.5 * s / ((double)NN * (double)NN));
    }
}

// ---------------- launch ------------------------------------------------------
extern "C" void kernel_launch(void* const* d_in, const int* in_sizes, int n_in,
                              void* d_out, int out_size)
{
    const float* node_reps = (const float*)d_in[0];
    const int*   in_idx    = (const int*)  d_in[1];
    const int*   in_edg    = (const int*)  d_in[2];
    const float* in_msk    = (const float*)d_in[3];
    const int*   out_idx   = (const int*)  d_in[4];
    const int*   out_edg   = (const int*)  d_in[5];
    const float* out_msk   = (const float*)d_in[6];
    const float* E1 = (const float*)d_in[7];
    const float* W1 = (const float*)d_in[8];
    const float* b1 = (const float*)d_in[9];
    const float* E2 = (const float*)d_in[10];
    const float* W2 = (const float*)d_in[11];
    const float* b2 = (const float*)d_in[12];
    const float* E3 = (const float*)d_in[13];
    const float* W3 = (const float*)d_in[14];
    const float* b3 = (const float*)d_in[15];

    float* hidden = (float*)d_out;                 // [N, D]
    float* wb1, *wb2, *wb3;
    cudaGetSymbolAddress((void**)&wb1, g_WB);      // base of g_WB[0]
    wb2 = wb1 + KDIM * DD;
    wb3 = wb2 + KDIM * DD;

    const dim3 gemm_grid((NN + BM - 1) / BM, DD / BN);  // 157 x 2
    const int  nblk = gemm_grid.x * gemm_grid.y;        // 314

    // weights + edge-count columns (layer-invariant)
    prep_wb<<<dim3(KDIM, 3), 256>>>(W1, E1, W2, E2, W3, E3);
    compute_c<<<(NN + 7) / 8, 256>>>(in_edg, in_msk, out_edg, out_msk);

    // layer 1: hidden = node_reps + [S,C] @ WB1 + 2*b1
    gather_sum<<<(NN + 3) / 4, 256>>>(node_reps, in_idx, in_msk, out_idx, out_msk);
    gemm_ep<0><<<gemm_grid, 256>>>(wb1, node_reps, b1, hidden, 0);

    // layers 2+3 share the aggregation of hidden; no stores, reduce-only
    gather_sum<<<(NN + 3) / 4, 256>>>(hidden, in_idx, in_msk, out_idx, out_msk);
    gemm_ep<1><<<gemm_grid, 256>>>(wb2, hidden, b2, nullptr, 0);      // mu
    gemm_ep<2><<<gemm_grid, 256>>>(wb3, hidden, b3, nullptr, nblk);   // logvar

    if (out_size > NN * DD)
        kld_final<<<1, 32>>>(2 * nblk, hidden + (size_t)NN * DD);
}

// round 3
// speedup vs baseline: 1.6068x; 1.6068x over previous
#include <cuda_runtime.h>
#include <cuda_bf16.h>
#include <math.h>
#include <stdint.h>

#define NN    20000
#define KK    16
#define DD    256
#define VV    64
#define KDIM  320
#define MT    157                 // M tiles of 128
#define MROWS (MT * 128)          // 20096 padded rows

// smem chunk layout: bf16 tiles [128 rows][64 k], padded row stride 72 elems = 144 B
#define RPAD 144
#define OA_H 0
#define OA_L 18432
#define OB_H 36864
#define OB_L 55296
#define BUF   73728
#define SMEM_REQ (2 * BUF)

// ---------------- scratch ------------------------------------------------------
__device__ __align__(16) __nv_bfloat16 g_Ah[MROWS * KDIM];
__device__ __align__(16) __nv_bfloat16 g_Al[MROWS * KDIM];
__device__ __align__(16) __nv_bfloat16 g_Bh[3][DD * KDIM];   // transposed: [n][k]
__device__ __align__(16) __nv_bfloat16 g_Bl[3][DD * KDIM];
__device__ float g_partials[1024];

// ---------------- helpers ------------------------------------------------------
__device__ __forceinline__ uint32_t smem_u32(const void* p) {
    uint32_t a;
    asm("{ .reg .u64 t; cvta.to.shared.u64 t, %1; cvt.u32.u64 %0, t; }" : "=r"(a) : "l"(p));
    return a;
}
__device__ __forceinline__ void split1(float x, __nv_bfloat16& h, __nv_bfloat16& l) {
    h = __float2bfloat16(x);
    l = __float2bfloat16(x - __bfloat162float(h));
}
#define CP16(sa, ga) asm volatile("cp.async.ca.shared.global [%0], [%1], 16;" :: "r"(sa), "l"(ga))
#define CP_COMMIT()  asm volatile("cp.async.commit_group;" ::: "memory")
#define CP_WAIT0()   asm volatile("cp.async.wait_group 0;" ::: "memory")

#define LDSM_X4(r, a) \
    asm volatile("ldmatrix.sync.aligned.m8n8.x4.shared.b16 {%0,%1,%2,%3}, [%4];" \
        : "=r"((r)[0]), "=r"((r)[1]), "=r"((r)[2]), "=r"((r)[3]) : "r"(a))
#define LDSM_X2(r, a) \
    asm volatile("ldmatrix.sync.aligned.m8n8.x2.shared.b16 {%0,%1}, [%2];" \
        : "=r"((r)[0]), "=r"((r)[1]) : "r"(a))
#define MMA_BF16(d, a, b) \
    asm volatile("mma.sync.aligned.m16n8k16.row.col.f32.bf16.bf16.f32 " \
        "{%0,%1,%2,%3}, {%4,%5,%6,%7}, {%8,%9}, {%0,%1,%2,%3};" \
        : "+f"((d)[0]), "+f"((d)[1]), "+f"((d)[2]), "+f"((d)[3]) \
        : "r"((a)[0]), "r"((a)[1]), "r"((a)[2]), "r"((a)[3]), "r"((b)[0]), "r"((b)[1]))

// ---------------- 1) combined weights, transposed + split ----------------------
__global__ void prep_wb(const float* __restrict__ W1, const float* __restrict__ E1,
                        const float* __restrict__ W2, const float* __restrict__ E2,
                        const float* __restrict__ W3, const float* __restrict__ E3)
{
    const int r = blockIdx.x;   // k 0..319
    const int l = blockIdx.y;
    const int d = threadIdx.x;  // n 0..255
    const float* W = (l == 0) ? W1 : (l == 1) ? W2 : W3;
    const float* E = (l == 0) ? E1 : (l == 1) ? E2 : E3;

    float x;
    if (r < DD) {
        x = W[r * DD + d];
    } else {
        const int v = r - DD;
        __shared__ float sE[DD];
        sE[d] = E[v * DD + d];
        __syncthreads();
        float acc = 0.f;
        #pragma unroll 8
        for (int j = 0; j < DD; j++) acc += sE[j] * W[(DD + j) * DD + d];
        x = acc;
    }
    __nv_bfloat16 h, lo; split1(x, h, lo);
    g_Bh[l][d * KDIM + r] = h;
    g_Bl[l][d * KDIM + r] = lo;
}

// ---------------- 2) edge-vocab histogram C[n,64] ------------------------------
__global__ void compute_c(const int* __restrict__ ie, const float* __restrict__ im,
                          const int* __restrict__ oe, const float* __restrict__ om)
{
    const int warp = threadIdx.x >> 5;
    const int lane = threadIdx.x & 31;
    const int n = blockIdx.x * 8 + warp;
    if (n >= NN) return;

    int e; float m;
    if (lane < KK) { e = ie[n * KK + lane];      m = im[n * KK + lane]; }
    else           { e = oe[n * KK + lane - KK]; m = om[n * KK + lane - KK]; }

    float c0 = 0.f, c1 = 0.f;
    #pragma unroll
    for (int s = 0; s < 32; s++) {
        const int   ev = __shfl_sync(0xFFFFFFFFu, e, s);
        const float mv = __shfl_sync(0xFFFFFFFFu, m, s);
        if (ev == lane)      c0 += mv;
        if (ev == lane + 32) c1 += mv;
    }
    __nv_bfloat16 h, lo;
    split1(c0, h, lo); g_Ah[n * KDIM + DD + lane] = h;      g_Al[n * KDIM + DD + lane] = lo;
    split1(c1, h, lo); g_Ah[n * KDIM + DD + 32 + lane] = h; g_Al[n * KDIM + DD + 32 + lane] = lo;
}

// ---------------- 3) gather-sum -> bf16 hi/lo -----------------------------------
__global__ void gather_sum(const float* __restrict__ src,
                           const int*   __restrict__ ii, const float* __restrict__ imk,
                           const int*   __restrict__ oi, const float* __restrict__ omk)
{
    const int n  = blockIdx.x * 4 + (threadIdx.x >> 6);
    const int c4 = (threadIdx.x & 63) * 4;
    if (n >= NN) return;

    float4 acc = make_float4(0.f, 0.f, 0.f, 0.f);
    #pragma unroll
    for (int k = 0; k < KK; k++) {
        const int   idx = ii[n * KK + k];
        const float m   = imk[n * KK + k];
        const float4 v  = *(const float4*)(src + (size_t)idx * DD + c4);
        acc.x += m * v.x; acc.y += m * v.y; acc.z += m * v.z; acc.w += m * v.w;
    }
    #pragma unroll
    for (int k = 0; k < KK; k++) {
        const int   idx = oi[n * KK + k];
        const float m   = omk[n * KK + k];
        const float4 v  = *(const float4*)(src + (size_t)idx * DD + c4);
        acc.x += m * v.x; acc.y += m * v.y; acc.z += m * v.z; acc.w += m * v.w;
    }
    const size_t o = (size_t)n * KDIM + c4;
    __nv_bfloat162 h2, l2;
    split1(acc.x, h2.x, l2.x); split1(acc.y, h2.y, l2.y);
    *(__nv_bfloat162*)(g_Ah + o)     = h2; *(__nv_bfloat162*)(g_Al + o)     = l2;
    split1(acc.z, h2.x, l2.x); split1(acc.w, h2.y, l2.y);
    *(__nv_bfloat162*)(g_Ah + o + 2) = h2; *(__nv_bfloat162*)(g_Al + o + 2) = l2;
}

// ---------------- 4) HMMA split-bf16 GEMM + fused epilogue ----------------------
// CTA: 128(M) x 128(N), K=320 in 5 chunks of 64, cp.async double buffered.
// 8 warps in 2(M) x 4(N); each warp 64x32 = 4x4 m16n8k16 tiles, 3 split terms.
template <int MODE>
__global__ __launch_bounds__(256, 1)
void gemm_m(int layer,
            const float* __restrict__ base,
            const float* __restrict__ bias,
            float* __restrict__ out, int poff)
{
    extern __shared__ char smc[];
    const uint32_t sb = smem_u32(smc);

    const int tid  = threadIdx.x;
    const int lane = tid & 31;
    const int wid  = tid >> 5;
    const int mw   = wid >> 2;          // 0..1
    const int nw   = wid & 3;           // 0..3
    const int m0   = blockIdx.x * 128;
    const int nb0  = blockIdx.y * 128;

    const __nv_bfloat16* __restrict__ Bh = g_Bh[layer];
    const __nv_bfloat16* __restrict__ Bl = g_Bl[layer];

    // --- chunk loader: global -> smem buffer b via cp.async ---
    const int lrow = tid >> 3, lu = tid & 7;
    auto load_chunk = [&](int c, int b) {
        const uint32_t sbase = sb + b * BUF;
        #pragma unroll
        for (int it = 0; it < 4; it++) {
            const int row = lrow + it * 32;
            const size_t goA = (size_t)(m0 + row) * KDIM + c * 64 + lu * 8;
            const size_t goB = (size_t)(nb0 + row) * KDIM + c * 64 + lu * 8;
            const uint32_t so = row * RPAD + lu * 16;
            CP16(sbase + OA_H + so, g_Ah + goA);
            CP16(sbase + OA_L + so, g_Al + goA);
            CP16(sbase + OB_H + so, Bh + goB);
            CP16(sbase + OB_L + so, Bl + goB);
        }
        CP_COMMIT();
    };

    float acc[4][4][4];
    #pragma unroll
    for (int i = 0; i < 4; i++)
        #pragma unroll
        for (int j = 0; j < 4; j++)
            #pragma unroll
            for (int f = 0; f < 4; f++) acc[i][j][f] = 0.f;

    load_chunk(0, 0);
    CP_WAIT0();
    __syncthreads();

    // per-lane ldmatrix base offsets
    const uint32_t a_rb = (mw * 64 + (lane & 15)) * RPAD + (lane >> 4) * 16;
    const uint32_t b_rb = (nw * 32 + (lane & 7)) * RPAD + ((lane >> 3) & 1) * 16;

    for (int c = 0; c < 5; c++) {
        if (c + 1 < 5) load_chunk(c + 1, (c + 1) & 1);
        const uint32_t bufs = sb + (c & 1) * BUF;

        #pragma unroll
        for (int s = 0; s < 4; s++) {           // 4 k16 steps per 64 chunk
            uint32_t ah[4][4], al[4][4], bh[4][2], bl[4][2];
            #pragma unroll
            for (int mi = 0; mi < 4; mi++) {
                const uint32_t ad = bufs + OA_H + a_rb + mi * (16 * RPAD) + s * 32;
                LDSM_X4(ah[mi], ad);
                LDSM_X4(al[mi], ad + (OA_L - OA_H));
            }
            #pragma unroll
            for (int ni = 0; ni < 4; ni++) {
                const uint32_t bd = bufs + OB_H + b_rb + ni * (8 * RPAD) + s * 32;
                LDSM_X2(bh[ni], bd);
                LDSM_X2(bl[ni], bd + (OB_L - OB_H));
            }
            #pragma unroll
            for (int mi = 0; mi < 4; mi++)
                #pragma unroll
                for (int ni = 0; ni < 4; ni++) {
                    MMA_BF16(acc[mi][ni], ah[mi], bh[ni]);
                    MMA_BF16(acc[mi][ni], al[mi], bh[ni]);
                    MMA_BF16(acc[mi][ni], ah[mi], bl[ni]);
                }
        }
        if (c + 1 < 5) { CP_WAIT0(); __syncthreads(); }
    }

    // --- epilogue ---
    const int g  = lane >> 2;
    const int q2 = (lane & 3) * 2;
    float s = 0.f;

    #pragma unroll
    for (int mi = 0; mi < 4; mi++) {
        const int r0 = m0 + mw * 64 + mi * 16 + g;
        const int r1 = r0 + 8;
        #pragma unroll
        for (int ni = 0; ni < 4; ni++) {
            const int cc = nb0 + nw * 32 + ni * 8 + q2;
            if (MODE == 0) {
                const float2 bv = *(const float2*)(bias + cc);
                if (r0 < NN) {
                    const float2 b0 = *(const float2*)(base + (size_t)r0 * DD + cc);
                    float2 o;
                    o.x = b0.x + acc[mi][ni][0] + 2.f * bv.x;
                    o.y = b0.y + acc[mi][ni][1] + 2.f * bv.y;
                    *(float2*)(out + (size_t)r0 * DD + cc) = o;
                }
                if (r1 < NN) {
                    const float2 b1 = *(const float2*)(base + (size_t)r1 * DD + cc);
                    float2 o;
                    o.x = b1.x + acc[mi][ni][2] + 2.f * bv.x;
                    o.y = b1.y + acc[mi][ni][3] + 2.f * bv.y;
                    *(float2*)(out + (size_t)r1 * DD + cc) = o;
                }
            } else {
                const float2 bv = *(const float2*)(bias + cc);
                if (r0 < NN) {
                    const float2 b0 = *(const float2*)(base + (size_t)r0 * DD + cc);
                    const float x0 = b0.x + acc[mi][ni][0] + 2.f * bv.x;
                    const float x1 = b0.y + acc[mi][ni][1] + 2.f * bv.y;
                    const float t0 = tanhf(x0), t1 = tanhf(x1);
                    if (MODE == 1) s -= t0 * t0 + t1 * t1;
                    else s += 2.f + 2.f * (t0 + t1) - expf(2.f * t0) - expf(2.f * t1);
                }
                if (r1 < NN) {
                    const float2 b1 = *(const float2*)(base + (size_t)r1 * DD + cc);
                    const float x0 = b1.x + acc[mi][ni][2] + 2.f * bv.x;
                    const float x1 = b1.y + acc[mi][ni][3] + 2.f * bv.y;
                    const float t0 = tanhf(x0), t1 = tanhf(x1);
                    if (MODE == 1) s -= t0 * t0 + t1 * t1;
                    else s += 2.f + 2.f * (t0 + t1) - expf(2.f * t0) - expf(2.f * t1);
                }
            }
        }
    }

    if (MODE != 0) {
        __shared__ float red[256];
        red[tid] = s;
        __syncthreads();
        #pragma unroll
        for (int o = 128; o > 0; o >>= 1) {
            if (tid < o) red[tid] += red[tid + o];
            __syncthreads();
        }
        if (tid == 0)
            g_partials[poff + blockIdx.y * gridDim.x + blockIdx.x] = red[0];
    }
}

// ---------------- 5) final kld reduction ----------------------------------------
__global__ void kld_final(int nslots, float* __restrict__ out_kld)
{
    if (threadIdx.x == 0 && blockIdx.x == 0) {
        double s = 0.0;
        for (int i = 0; i < nslots; i++) s += (double)g_partials[i];
        out_kld[0] = (float)(-0.5 * s / ((double)NN * (double)NN));
    }
}

// ---------------- launch ----------------------------------------------------------
extern "C" void kernel_launch(void* const* d_in, const int* in_sizes, int n_in,
                              void* d_out, int out_size)
{
    const float* node_reps = (const float*)d_in[0];
    const int*   in_idx    = (const int*)  d_in[1];
    const int*   in_edg    = (const int*)  d_in[2];
    const float* in_msk    = (const float*)d_in[3];
    const int*   out_idx   = (const int*)  d_in[4];
    const int*   out_edg   = (const int*)  d_in[5];
    const float* out_msk   = (const float*)d_in[6];
    const float* E1 = (const float*)d_in[7];
    const float* W1 = (const float*)d_in[8];
    const float* b1 = (const float*)d_in[9];
    const float* E2 = (const float*)d_in[10];
    const float* W2 = (const float*)d_in[11];
    const float* b2 = (const float*)d_in[12];
    const float* E3 = (const float*)d_in[13];
    const float* W3 = (const float*)d_in[14];
    const float* b3 = (const float*)d_in[15];

    float* hidden = (float*)d_out;

    cudaFuncSetAttribute(gemm_m<0>, cudaFuncAttributeMaxDynamicSharedMemorySize, SMEM_REQ);
    cudaFuncSetAttribute(gemm_m<1>, cudaFuncAttributeMaxDynamicSharedMemorySize, SMEM_REQ);
    cudaFuncSetAttribute(gemm_m<2>, cudaFuncAttributeMaxDynamicSharedMemorySize, SMEM_REQ);

    const dim3 gg(MT, 2);

    prep_wb<<<dim3(KDIM, 3), 256>>>(W1, E1, W2, E2, W3, E3);
    compute_c<<<(NN + 7) / 8, 256>>>(in_edg, in_msk, out_edg, out_msk);

    gather_sum<<<(NN + 3) / 4, 256>>>(node_reps, in_idx, in_msk, out_idx, out_msk);
    gemm_m<0><<<gg, 256, SMEM_REQ>>>(0, node_reps, b1, hidden, 0);

    gather_sum<<<(NN + 3) / 4, 256>>>(hidden, in_idx, in_msk, out_idx, out_msk);
    gemm_m<1><<<gg, 256, SMEM_REQ>>>(1, hidden, b2, nullptr, 0);
    gemm_m<2><<<gg, 256, SMEM_REQ>>>(2, hidden, b3, nullptr, 2 * MT);

    if (out_size > NN * DD)
        kld_final<<<1, 32>>>(4 * MT, hidden + (size_t)NN * DD);
}

// round 4
// speedup vs baseline: 1.9922x; 1.2398x over previous
#include <cuda_runtime.h>
#include <cuda_bf16.h>
#include <cuda_fp16.h>
#include <math.h>
#include <stdint.h>

#define NN    20000
#define KK    16
#define DD    256
#define VV    64
#define KDIM  320
#define MT    157
#define MROWS (MT * 128)

#define RPAD 144                  // smem row stride bytes (72 bf16)

// kernel A (hidden): A + B1 tiles
#define A_OAH 0
#define A_OAL 18432
#define A_OBH 36864
#define A_OBL 55296
#define A_BUF 73728
#define SMEM_A (2 * A_BUF)
// kernel B (mu+logvar fused): A + B2 + B3 tiles
#define B_OAH  0
#define B_OAL  18432
#define B_O2H  36864
#define B_O2L  55296
#define B_O3H  73728
#define B_O3L  92160
#define B_BUF  110592
#define SMEM_B (2 * B_BUF)

// ---------------- scratch -------------------------------------------------------
__device__ __align__(16) __nv_bfloat16 g_Ah[MROWS * KDIM];
__device__ __align__(16) __nv_bfloat16 g_Al[MROWS * KDIM];
__device__ __align__(16) __nv_bfloat16 g_Bh[3][DD * KDIM];   // transposed [n][k]
__device__ __align__(16) __nv_bfloat16 g_Bl[3][DD * KDIM];
__device__ __align__(16) __half        g_X16[NN * DD];       // fp16 gather source
__device__ float g_partials[1024];

// ---------------- helpers -------------------------------------------------------
__device__ __forceinline__ uint32_t smem_u32(const void* p) {
    uint32_t a;
    asm("{ .reg .u64 t; cvta.to.shared.u64 t, %1; cvt.u32.u64 %0, t; }" : "=r"(a) : "l"(p));
    return a;
}
__device__ __forceinline__ void split1(float x, __nv_bfloat16& h, __nv_bfloat16& l) {
    h = __float2bfloat16(x);
    l = __float2bfloat16(x - __bfloat162float(h));
}
#define CP16(sa, ga) asm volatile("cp.async.ca.shared.global [%0], [%1], 16;" :: "r"(sa), "l"(ga))
#define CP_COMMIT()  asm volatile("cp.async.commit_group;" ::: "memory")
#define CP_WAIT0()   asm volatile("cp.async.wait_group 0;" ::: "memory")
#define LDSM_X4(r, a) \
    asm volatile("ldmatrix.sync.aligned.m8n8.x4.shared.b16 {%0,%1,%2,%3}, [%4];" \
        : "=r"((r)[0]), "=r"((r)[1]), "=r"((r)[2]), "=r"((r)[3]) : "r"(a))
#define LDSM_X2(r, a) \
    asm volatile("ldmatrix.sync.aligned.m8n8.x2.shared.b16 {%0,%1}, [%2];" \
        : "=r"((r)[0]), "=r"((r)[1]) : "r"(a))
#define MMA_BF16(d, a, b) \
    asm volatile("mma.sync.aligned.m16n8k16.row.col.f32.bf16.bf16.f32 " \
        "{%0,%1,%2,%3}, {%4,%5,%6,%7}, {%8,%9}, {%0,%1,%2,%3};" \
        : "+f"((d)[0]), "+f"((d)[1]), "+f"((d)[2]), "+f"((d)[3]) \
        : "r"((a)[0]), "r"((a)[1]), "r"((a)[2]), "r"((a)[3]), "r"((b)[0]), "r"((b)[1]))

// ---------------- 0) fp32 -> fp16 convert ---------------------------------------
__global__ void conv16(const float* __restrict__ src)
{
    const int i = blockIdx.x * blockDim.x + threadIdx.x;   // over NN*DD/4
    if (i >= NN * DD / 4) return;
    const float4 v = ((const float4*)src)[i];
    __half2 a = __floats2half2_rn(v.x, v.y);
    __half2 b = __floats2half2_rn(v.z, v.w);
    uint2 u; u.x = *(uint32_t*)&a; u.y = *(uint32_t*)&b;
    ((uint2*)g_X16)[i] = u;
}

// ---------------- 1) combined weights, transposed + split ------------------------
__global__ void prep_wb(const float* __restrict__ W1, const float* __restrict__ E1,
                        const float* __restrict__ W2, const float* __restrict__ E2,
                        const float* __restrict__ W3, const float* __restrict__ E3)
{
    const int r = blockIdx.x;   // k 0..319
    const int l = blockIdx.y;
    const int d = threadIdx.x;  // n 0..255
    const float* W = (l == 0) ? W1 : (l == 1) ? W2 : W3;
    const float* E = (l == 0) ? E1 : (l == 1) ? E2 : E3;

    float x;
    if (r < DD) {
        x = W[r * DD + d];
    } else {
        const int v = r - DD;
        __shared__ float sE[DD];
        sE[d] = E[v * DD + d];
        __syncthreads();
        float acc = 0.f;
        #pragma unroll 8
        for (int j = 0; j < DD; j++) acc += sE[j] * W[(DD + j) * DD + d];
        x = acc;
    }
    __nv_bfloat16 h, lo; split1(x, h, lo);
    g_Bh[l][d * KDIM + r] = h;
    g_Bl[l][d * KDIM + r] = lo;
}

// ---------------- 2) edge-vocab histogram C[n,64] --------------------------------
__global__ void compute_c(const int* __restrict__ ie, const float* __restrict__ im,
                          const int* __restrict__ oe, const float* __restrict__ om)
{
    const int warp = threadIdx.x >> 5;
    const int lane = threadIdx.x & 31;
    const int n = blockIdx.x * 8 + warp;
    if (n >= NN) return;

    int e; float m;
    if (lane < KK) { e = ie[n * KK + lane];      m = im[n * KK + lane]; }
    else           { e = oe[n * KK + lane - KK]; m = om[n * KK + lane - KK]; }

    float c0 = 0.f, c1 = 0.f;
    #pragma unroll
    for (int s = 0; s < 32; s++) {
        const int   ev = __shfl_sync(0xFFFFFFFFu, e, s);
        const float mv = __shfl_sync(0xFFFFFFFFu, m, s);
        if (ev == lane)      c0 += mv;
        if (ev == lane + 32) c1 += mv;
    }
    __nv_bfloat16 h, lo;
    split1(c0, h, lo); g_Ah[n * KDIM + DD + lane] = h;      g_Al[n * KDIM + DD + lane] = lo;
    split1(c1, h, lo); g_Ah[n * KDIM + DD + 32 + lane] = h; g_Al[n * KDIM + DD + 32 + lane] = lo;
}

// ---------------- 3) fp16 gather-sum -> bf16 hi/lo --------------------------------
// one warp per node; lane owns 8 columns (16B per neighbor row).
__global__ void gather16(const int*   __restrict__ ii, const float* __restrict__ imk,
                         const int*   __restrict__ oi, const float* __restrict__ omk)
{
    const int warp = threadIdx.x >> 5;
    const int lane = threadIdx.x & 31;
    const int n = blockIdx.x * 8 + warp;
    if (n >= NN) return;

    int e; float m;
    if (lane < KK) { e = ii[n * KK + lane];      m = imk[n * KK + lane]; }
    else           { e = oi[n * KK + lane - KK]; m = omk[n * KK + lane - KK]; }

    float acc[8];
    #pragma unroll
    for (int j = 0; j < 8; j++) acc[j] = 0.f;

    #pragma unroll 8
    for (int k = 0; k < 32; k++) {
        const int   id = __shfl_sync(0xFFFFFFFFu, e, k);
        const float mm = __shfl_sync(0xFFFFFFFFu, m, k);
        const uint4 v = *(const uint4*)(g_X16 + (size_t)id * DD + lane * 8);
        const __half2* hp = (const __half2*)&v;
        #pragma unroll
        for (int j = 0; j < 4; j++) {
            const float2 f = __half22float2(hp[j]);
            acc[2 * j]     += mm * f.x;
            acc[2 * j + 1] += mm * f.y;
        }
    }
    __nv_bfloat16 hb[8], lb[8];
    #pragma unroll
    for (int j = 0; j < 8; j++) split1(acc[j], hb[j], lb[j]);
    const size_t o = (size_t)n * KDIM + lane * 8;
    *(uint4*)(g_Ah + o) = *(uint4*)hb;
    *(uint4*)(g_Al + o) = *(uint4*)lb;
}

// ---------------- 4a) GEMM hidden: 128x128 CTA, 16 warps, fused epilogue ----------
__global__ __launch_bounds__(512, 1)
void gemm_h(const float* __restrict__ base,
            const float* __restrict__ bias,
            float* __restrict__ out)
{
    extern __shared__ char smc[];
    const uint32_t sb = smem_u32(smc);

    const int tid  = threadIdx.x;
    const int lane = tid & 31;
    const int wid  = tid >> 5;
    const int mw   = wid >> 2;          // 0..3
    const int nw   = wid & 3;           // 0..3
    const int m0   = blockIdx.x * 128;
    const int nb0  = blockIdx.y * 128;

    const __nv_bfloat16* __restrict__ Bh = g_Bh[0];
    const __nv_bfloat16* __restrict__ Bl = g_Bl[0];

    auto load_chunk = [&](int c, int b) {
        const uint32_t s0 = sb + b * A_BUF;
        for (int i = tid; i < 1024; i += 512) {
            const int row = i >> 3, u = i & 7;
            const size_t go = (size_t)(m0 + row) * KDIM + c * 64 + u * 8;
            const uint32_t so = row * RPAD + u * 16;
            CP16(s0 + A_OAH + so, g_Ah + go);
            CP16(s0 + A_OAL + so, g_Al + go);
        }
        for (int i = tid; i < 1024; i += 512) {
            const int row = i >> 3, u = i & 7;
            const size_t go = (size_t)(nb0 + row) * KDIM + c * 64 + u * 8;
            const uint32_t so = row * RPAD + u * 16;
            CP16(s0 + A_OBH + so, Bh + go);
            CP16(s0 + A_OBL + so, Bl + go);
        }
        CP_COMMIT();
    };

    float acc[2][4][4];
    #pragma unroll
    for (int i = 0; i < 2; i++)
        #pragma unroll
        for (int j = 0; j < 4; j++)
            #pragma unroll
            for (int f = 0; f < 4; f++) acc[i][j][f] = 0.f;

    load_chunk(0, 0);
    CP_WAIT0();
    __syncthreads();

    const uint32_t a_rb = (mw * 32 + (lane & 15)) * RPAD + (lane >> 4) * 16;
    const uint32_t b_rb = (nw * 32 + (lane & 7)) * RPAD + ((lane >> 3) & 1) * 16;

    for (int c = 0; c < 5; c++) {
        if (c + 1 < 5) load_chunk(c + 1, (c + 1) & 1);
        const uint32_t bufs = sb + (c & 1) * A_BUF;

        #pragma unroll
        for (int s = 0; s < 4; s++) {
            uint32_t bh[4][2], bl[4][2];
            #pragma unroll
            for (int ni = 0; ni < 4; ni++) {
                const uint32_t bd = bufs + A_OBH + b_rb + ni * (8 * RPAD) + s * 32;
                LDSM_X2(bh[ni], bd);
                LDSM_X2(bl[ni], bd + (A_OBL - A_OBH));
            }
            #pragma unroll
            for (int mi = 0; mi < 2; mi++) {
                uint32_t ah[4], al[4];
                const uint32_t ad = bufs + A_OAH + a_rb + mi * (16 * RPAD) + s * 32;
                LDSM_X4(ah, ad);
                LDSM_X4(al, ad + (A_OAL - A_OAH));
                #pragma unroll
                for (int ni = 0; ni < 4; ni++) {
                    MMA_BF16(acc[mi][ni], ah, bh[ni]);
                    MMA_BF16(acc[mi][ni], al, bh[ni]);
                    MMA_BF16(acc[mi][ni], ah, bl[ni]);
                }
            }
        }
        if (c + 1 < 5) { CP_WAIT0(); __syncthreads(); }
    }

    // epilogue: out fp32 + fp16 copy for next gather
    const int g  = lane >> 2;
    const int q2 = (lane & 3) * 2;
    #pragma unroll
    for (int mi = 0; mi < 2; mi++) {
        const int r0 = m0 + mw * 32 + mi * 16 + g;
        #pragma unroll
        for (int ni = 0; ni < 4; ni++) {
            const int cc = nb0 + nw * 32 + ni * 8 + q2;
            const float2 bv = *(const float2*)(bias + cc);
            #pragma unroll
            for (int h = 0; h < 2; h++) {
                const int r = r0 + h * 8;
                if (r < NN) {
                    const float2 b0 = *(const float2*)(base + (size_t)r * DD + cc);
                    float2 o;
                    o.x = b0.x + acc[mi][ni][2 * h + 0] + 2.f * bv.x;
                    o.y = b0.y + acc[mi][ni][2 * h + 1] + 2.f * bv.y;
                    *(float2*)(out + (size_t)r * DD + cc) = o;
                    const __half2 h2 = __floats2half2_rn(o.x, o.y);
                    *(uint32_t*)(g_X16 + (size_t)r * DD + cc) = *(const uint32_t*)&h2;
                }
            }
        }
    }
}

// ---------------- 4b) fused mu+logvar GEMM (no stores, kld partials) --------------
__global__ __launch_bounds__(512, 1)
void gemm_kld(const float* __restrict__ base,
              const float* __restrict__ b2, const float* __restrict__ b3)
{
    extern __shared__ char smc[];
    const uint32_t sb = smem_u32(smc);

    const int tid  = threadIdx.x;
    const int lane = tid & 31;
    const int wid  = tid >> 5;
    const int mw   = wid >> 2;
    const int nw   = wid & 3;
    const int m0   = blockIdx.x * 128;
    const int nb0  = blockIdx.y * 128;

    auto load_chunk = [&](int c, int b) {
        const uint32_t s0 = sb + b * B_BUF;
        for (int i = tid; i < 1024; i += 512) {
            const int row = i >> 3, u = i & 7;
            const size_t go = (size_t)(m0 + row) * KDIM + c * 64 + u * 8;
            const uint32_t so = row * RPAD + u * 16;
            CP16(s0 + B_OAH + so, g_Ah + go);
            CP16(s0 + B_OAL + so, g_Al + go);
        }
        for (int i = tid; i < 1024; i += 512) {
            const int row = i >> 3, u = i & 7;
            const size_t go = (size_t)(nb0 + row) * KDIM + c * 64 + u * 8;
            const uint32_t so = row * RPAD + u * 16;
            CP16(s0 + B_O2H + so, g_Bh[1] + go);
            CP16(s0 + B_O2L + so, g_Bl[1] + go);
            CP16(s0 + B_O3H + so, g_Bh[2] + go);
            CP16(s0 + B_O3L + so, g_Bl[2] + go);
        }
        CP_COMMIT();
    };

    float acc2[2][4][4], acc3[2][4][4];
    #pragma unroll
    for (int i = 0; i < 2; i++)
        #pragma unroll
        for (int j = 0; j < 4; j++)
            #pragma unroll
            for (int f = 0; f < 4; f++) { acc2[i][j][f] = 0.f; acc3[i][j][f] = 0.f; }

    load_chunk(0, 0);
    CP_WAIT0();
    __syncthreads();

    const uint32_t a_rb = (mw * 32 + (lane & 15)) * RPAD + (lane >> 4) * 16;
    const uint32_t b_rb = (nw * 32 + (lane & 7)) * RPAD + ((lane >> 3) & 1) * 16;

    for (int c = 0; c < 5; c++) {
        if (c + 1 < 5) load_chunk(c + 1, (c + 1) & 1);
        const uint32_t bufs = sb + (c & 1) * B_BUF;

        #pragma unroll
        for (int s = 0; s < 4; s++) {
            uint32_t b2h[4][2], b2l[4][2], b3h[4][2], b3l[4][2];
            #pragma unroll
            for (int ni = 0; ni < 4; ni++) {
                const uint32_t bd = bufs + b_rb + ni * (8 * RPAD) + s * 32;
                LDSM_X2(b2h[ni], bd + B_O2H);
                LDSM_X2(b2l[ni], bd + B_O2L);
                LDSM_X2(b3h[ni], bd + B_O3H);
                LDSM_X2(b3l[ni], bd + B_O3L);
            }
            #pragma unroll
            for (int mi = 0; mi < 2; mi++) {
                uint32_t ah[4], al[4];
                const uint32_t ad = bufs + B_OAH + a_rb + mi * (16 * RPAD) + s * 32;
                LDSM_X4(ah, ad);
                LDSM_X4(al, ad + (B_OAL - B_OAH));
                #pragma unroll
                for (int ni = 0; ni < 4; ni++) {
                    MMA_BF16(acc2[mi][ni], ah, b2h[ni]);
                    MMA_BF16(acc2[mi][ni], al, b2h[ni]);
                    MMA_BF16(acc2[mi][ni], ah, b2l[ni]);
                    MMA_BF16(acc3[mi][ni], ah, b3h[ni]);
                    MMA_BF16(acc3[mi][ni], al, b3h[ni]);
                    MMA_BF16(acc3[mi][ni], ah, b3l[ni]);
                }
            }
        }
        if (c + 1 < 5) { CP_WAIT0(); __syncthreads(); }
    }

    // epilogue: kld partial sums only
    const int g  = lane >> 2;
    const int q2 = (lane & 3) * 2;
    float smu = 0.f, slv = 0.f;
    #pragma unroll
    for (int mi = 0; mi < 2; mi++) {
        const int r0 = m0 + mw * 32 + mi * 16 + g;
        #pragma unroll
        for (int ni = 0; ni < 4; ni++) {
            const int cc = nb0 + nw * 32 + ni * 8 + q2;
            const float2 v2 = *(const float2*)(b2 + cc);
            const float2 v3 = *(const float2*)(b3 + cc);
            #pragma unroll
            for (int h = 0; h < 2; h++) {
                const int r = r0 + h * 8;
                if (r < NN) {
                    const float2 b0 = *(const float2*)(base + (size_t)r * DD + cc);
                    const float xm0 = b0.x + acc2[mi][ni][2 * h + 0] + 2.f * v2.x;
                    const float xm1 = b0.y + acc2[mi][ni][2 * h + 1] + 2.f * v2.y;
                    const float xl0 = b0.x + acc3[mi][ni][2 * h + 0] + 2.f * v3.x;
                    const float xl1 = b0.y + acc3[mi][ni][2 * h + 1] + 2.f * v3.y;
                    const float tm0 = tanhf(xm0), tm1 = tanhf(xm1);
                    const float tl0 = tanhf(xl0), tl1 = tanhf(xl1);
                    smu -= tm0 * tm0 + tm1 * tm1;
                    slv += 2.f + 2.f * (tl0 + tl1) - expf(2.f * tl0) - expf(2.f * tl1);
                }
            }
        }
    }

    __syncthreads();                       // smem buffers no longer needed
    float* red = (float*)smc;
    red[tid] = smu;
    red[512 + tid] = slv;
    __syncthreads();
    #pragma unroll
    for (int o = 256; o > 0; o >>= 1) {
        if (tid < o) { red[tid] += red[tid + o]; red[512 + tid] += red[512 + tid + o]; }
        __syncthreads();
    }
    if (tid == 0) {
        const int bidx = blockIdx.y * gridDim.x + blockIdx.x;
        g_partials[bidx] = red[0] + red[512];
    }
}

// ---------------- 5) final kld reduction -------------------------------------------
__global__ void kld_final(int nslots, float* __restrict__ out_kld)
{
    if (threadIdx.x == 0 && blockIdx.x == 0) {
        double s = 0.0;
        for (int i = 0; i < nslots; i++) s += (double)g_partials[i];
        out_kld[0] = (float)(-0.5 * s / ((double)NN * (double)NN));
    }
}

// ---------------- launch -------------------------------------------------------------
extern "C" void kernel_launch(void* const* d_in, const int* in_sizes, int n_in,
                              void* d_out, int out_size)
{
    const float* node_reps = (const float*)d_in[0];
    const int*   in_idx    = (const int*)  d_in[1];
    const int*   in_edg    = (const int*)  d_in[2];
    const float* in_msk    = (const float*)d_in[3];
    const int*   out_idx   = (const int*)  d_in[4];
    const int*   out_edg   = (const int*)  d_in[5];
    const float* out_msk   = (const float*)d_in[6];
    const float* E1 = (const float*)d_in[7];
    const float* W1 = (const float*)d_in[8];
    const float* b1 = (const float*)d_in[9];
    const float* E2 = (const float*)d_in[10];
    const float* W2 = (const float*)d_in[11];
    const float* b2 = (const float*)d_in[12];
    const float* E3 = (const float*)d_in[13];
    const float* W3 = (const float*)d_in[14];
    const float* b3 = (const float*)d_in[15];

    float* hidden = (float*)d_out;

    cudaFuncSetAttribute(gemm_h,   cudaFuncAttributeMaxDynamicSharedMemorySize, SMEM_A);
    cudaFuncSetAttribute(gemm_kld, cudaFuncAttributeMaxDynamicSharedMemorySize, SMEM_B);

    const dim3 gg(MT, 2);

    conv16<<<(NN * DD / 4 + 255) / 256, 256>>>(node_reps);
    prep_wb<<<dim3(KDIM, 3), 256>>>(W1, E1, W2, E2, W3, E3);
    compute_c<<<(NN + 7) / 8, 256>>>(in_edg, in_msk, out_edg, out_msk);

    gather16<<<(NN + 7) / 8, 256>>>(in_idx, in_msk, out_idx, out_msk);
    gemm_h<<<gg, 512, SMEM_A>>>(node_reps, b1, hidden);

    gather16<<<(NN + 7) / 8, 256>>>(in_idx, in_msk, out_idx, out_msk);
    gemm_kld<<<gg, 512, SMEM_B>>>(hidden, b2, b3);

    if (out_size > NN * DD)
        kld_final<<<1, 32>>>(2 * MT, hidden + (size_t)NN * DD);
}

// round 5
// speedup vs baseline: 2.5147x; 1.2623x over previous
#include <cuda_runtime.h>
#include <cuda_fp16.h>
#include <math.h>
#include <stdint.h>

#define NN    20000
#define KK    16
#define DD    256
#define VV    64
#define KDIM  320
#define MT    157
#define MROWS (MT * 128)

#define RPAD 144                  // smem row stride bytes (72 fp16)

// gemm_h smem: A + B1h + B1l
#define A_OA  0
#define A_OBH 18432
#define A_OBL 36864
#define A_BUF 55296
#define SMEM_A (2 * A_BUF)
// gemm_kld smem: A + B2h + B2l + B3h + B3l
#define B_OA  0
#define B_O2H 18432
#define B_O2L 36864
#define B_O3H 55296
#define B_O3L 73728
#define B_BUF 92160
#define SMEM_B (2 * B_BUF)

// prologue grid partition
#define PB_CONV 5000              // NN*DD/4 / 256
#define PB_WB   960               // 320 x 3
#define PB_C    2500              // NN / 8

// ---------------- scratch -------------------------------------------------------
__device__ __align__(16) __half g_A16[MROWS * KDIM];        // fp16 A (gather + C cols)
__device__ __align__(16) __half g_B16h[3][DD * KDIM];       // B transposed [n][k], hi
__device__ __align__(16) __half g_B16l[3][DD * KDIM];       // lo
__device__ __align__(16) __half g_X16[NN * DD];             // fp16 gather source
__device__ float g_partials[1024];

// ---------------- helpers -------------------------------------------------------
__device__ __forceinline__ uint32_t smem_u32(const void* p) {
    uint32_t a;
    asm("{ .reg .u64 t; cvta.to.shared.u64 t, %1; cvt.u32.u64 %0, t; }" : "=r"(a) : "l"(p));
    return a;
}
__device__ __forceinline__ void split1h(float x, __half& h, __half& l) {
    h = __float2half_rn(x);
    l = __float2half_rn(x - __half2float(h));
}
#define CP16(sa, ga) asm volatile("cp.async.ca.shared.global [%0], [%1], 16;" :: "r"(sa), "l"(ga))
#define CP_COMMIT()  asm volatile("cp.async.commit_group;" ::: "memory")
#define CP_WAIT0()   asm volatile("cp.async.wait_group 0;" ::: "memory")
#define LDSM_X4(r, a) \
    asm volatile("ldmatrix.sync.aligned.m8n8.x4.shared.b16 {%0,%1,%2,%3}, [%4];" \
        : "=r"((r)[0]), "=r"((r)[1]), "=r"((r)[2]), "=r"((r)[3]) : "r"(a))
#define LDSM_X2(r, a) \
    asm volatile("ldmatrix.sync.aligned.m8n8.x2.shared.b16 {%0,%1}, [%2];" \
        : "=r"((r)[0]), "=r"((r)[1]) : "r"(a))
#define MMA_F16(d, a, b) \
    asm volatile("mma.sync.aligned.m16n8k16.row.col.f32.f16.f16.f32 " \
        "{%0,%1,%2,%3}, {%4,%5,%6,%7}, {%8,%9}, {%0,%1,%2,%3};" \
        : "+f"((d)[0]), "+f"((d)[1]), "+f"((d)[2]), "+f"((d)[3]) \
        : "r"((a)[0]), "r"((a)[1]), "r"((a)[2]), "r"((a)[3]), "r"((b)[0]), "r"((b)[1]))

// ---------------- 0) fused prologue: conv16 | prep_wb | compute_c ----------------
__global__ void prep_all(const float* __restrict__ src,
                         const float* __restrict__ W1, const float* __restrict__ E1,
                         const float* __restrict__ W2, const float* __restrict__ E2,
                         const float* __restrict__ W3, const float* __restrict__ E3,
                         const int* __restrict__ ie, const float* __restrict__ im,
                         const int* __restrict__ oe, const float* __restrict__ om)
{
    const int b = blockIdx.x;
    const int tid = threadIdx.x;

    if (b < PB_CONV) {
        // fp32 -> fp16 node table
        const int i = b * 256 + tid;
        const float4 v = ((const float4*)src)[i];
        const __half2 a2 = __floats2half2_rn(v.x, v.y);
        const __half2 b2 = __floats2half2_rn(v.z, v.w);
        uint2 u; u.x = *(const uint32_t*)&a2; u.y = *(const uint32_t*)&b2;
        ((uint2*)g_X16)[i] = u;
        return;
    }
    if (b < PB_CONV + PB_WB) {
        // combined weights (transposed) -> fp16 h+l
        const int rb = b - PB_CONV;
        const int r = rb % KDIM;          // k 0..319
        const int l = rb / KDIM;          // layer
        const int d = tid;                // n 0..255
        const float* W = (l == 0) ? W1 : (l == 1) ? W2 : W3;
        const float* E = (l == 0) ? E1 : (l == 1) ? E2 : E3;
        float x;
        if (r < DD) {
            x = W[r * DD + d];
        } else {
            const int v = r - DD;
            __shared__ float sE[DD];
            sE[d] = E[v * DD + d];
            __syncthreads();
            float acc = 0.f;
            #pragma unroll 8
            for (int j = 0; j < DD; j++) acc += sE[j] * W[(DD + j) * DD + d];
            x = acc;
        }
        __half h, lo; split1h(x, h, lo);
        g_B16h[l][d * KDIM + r] = h;
        g_B16l[l][d * KDIM + r] = lo;
        return;
    }
    // edge-vocab histogram C[n, 64] -> fp16 A columns 256..319
    const int warp = tid >> 5;
    const int lane = tid & 31;
    const int n = (b - PB_CONV - PB_WB) * 8 + warp;
    if (n >= NN) return;

    int e; float m;
    if (lane < KK) { e = ie[n * KK + lane];      m = im[n * KK + lane]; }
    else           { e = oe[n * KK + lane - KK]; m = om[n * KK + lane - KK]; }

    float c0 = 0.f, c1 = 0.f;
    #pragma unroll
    for (int s = 0; s < 32; s++) {
        const int   ev = __shfl_sync(0xFFFFFFFFu, e, s);
        const float mv = __shfl_sync(0xFFFFFFFFu, m, s);
        if (ev == lane)      c0 += mv;
        if (ev == lane + 32) c1 += mv;
    }
    g_A16[n * KDIM + DD + lane]      = __float2half_rn(c0);
    g_A16[n * KDIM + DD + 32 + lane] = __float2half_rn(c1);
}

// ---------------- 1) fp16 gather-sum -> fp16 A -----------------------------------
__global__ void gather16(const int*   __restrict__ ii, const float* __restrict__ imk,
                         const int*   __restrict__ oi, const float* __restrict__ omk)
{
    const int warp = threadIdx.x >> 5;
    const int lane = threadIdx.x & 31;
    const int n = blockIdx.x * 8 + warp;
    if (n >= NN) return;

    int e; float m;
    if (lane < KK) { e = ii[n * KK + lane];      m = imk[n * KK + lane]; }
    else           { e = oi[n * KK + lane - KK]; m = omk[n * KK + lane - KK]; }

    float acc[8];
    #pragma unroll
    for (int j = 0; j < 8; j++) acc[j] = 0.f;

    #pragma unroll 8
    for (int k = 0; k < 32; k++) {
        const int   id = __shfl_sync(0xFFFFFFFFu, e, k);
        const float mm = __shfl_sync(0xFFFFFFFFu, m, k);
        const uint4 v = *(const uint4*)(g_X16 + (size_t)id * DD + lane * 8);
        const __half2* hp = (const __half2*)&v;
        #pragma unroll
        for (int j = 0; j < 4; j++) {
            const float2 f = __half22float2(hp[j]);
            acc[2 * j]     += mm * f.x;
            acc[2 * j + 1] += mm * f.y;
        }
    }
    __half hb[8];
    #pragma unroll
    for (int j = 0; j < 8; j++) hb[j] = __float2half_rn(acc[j]);
    *(uint4*)(g_A16 + (size_t)n * KDIM + lane * 8) = *(const uint4*)hb;
}

// ---------------- 2a) GEMM hidden: 128x128 CTA, 16 warps, 2-term fp16 ------------
__global__ __launch_bounds__(512, 1)
void gemm_h(const float* __restrict__ base,
            const float* __restrict__ bias,
            float* __restrict__ out)
{
    extern __shared__ char smc[];
    const uint32_t sb = smem_u32(smc);

    const int tid  = threadIdx.x;
    const int lane = tid & 31;
    const int wid  = tid >> 5;
    const int mw   = wid >> 2;
    const int nw   = wid & 3;
    const int m0   = blockIdx.x * 128;
    const int nb0  = blockIdx.y * 128;

    const __half* __restrict__ Bh = g_B16h[0];
    const __half* __restrict__ Bl = g_B16l[0];

    auto load_chunk = [&](int c, int bsel) {
        const uint32_t s0 = sb + bsel * A_BUF;
        for (int i = tid; i < 1024; i += 512) {
            const int row = i >> 3, u = i & 7;
            const uint32_t so = row * RPAD + u * 16;
            CP16(s0 + A_OA + so, g_A16 + (size_t)(m0 + row) * KDIM + c * 64 + u * 8);
        }
        for (int i = tid; i < 1024; i += 512) {
            const int row = i >> 3, u = i & 7;
            const size_t go = (size_t)(nb0 + row) * KDIM + c * 64 + u * 8;
            const uint32_t so = row * RPAD + u * 16;
            CP16(s0 + A_OBH + so, Bh + go);
            CP16(s0 + A_OBL + so, Bl + go);
        }
        CP_COMMIT();
    };

    float acc[2][4][4];
    #pragma unroll
    for (int i = 0; i < 2; i++)
        #pragma unroll
        for (int j = 0; j < 4; j++)
            #pragma unroll
            for (int f = 0; f < 4; f++) acc[i][j][f] = 0.f;

    load_chunk(0, 0);
    CP_WAIT0();
    __syncthreads();

    const uint32_t a_rb = (mw * 32 + (lane & 15)) * RPAD + (lane >> 4) * 16;
    const uint32_t b_rb = (nw * 32 + (lane & 7)) * RPAD + ((lane >> 3) & 1) * 16;

    for (int c = 0; c < 5; c++) {
        if (c + 1 < 5) load_chunk(c + 1, (c + 1) & 1);
        const uint32_t bufs = sb + (c & 1) * A_BUF;

        #pragma unroll
        for (int s = 0; s < 4; s++) {
            uint32_t bh[4][2], bl[4][2];
            #pragma unroll
            for (int ni = 0; ni < 4; ni++) {
                const uint32_t bd = bufs + b_rb + ni * (8 * RPAD) + s * 32;
                LDSM_X2(bh[ni], bd + A_OBH);
                LDSM_X2(bl[ni], bd + A_OBL);
            }
            #pragma unroll
            for (int mi = 0; mi < 2; mi++) {
                uint32_t a[4];
                LDSM_X4(a, bufs + A_OA + a_rb + mi * (16 * RPAD) + s * 32);
                #pragma unroll
                for (int ni = 0; ni < 4; ni++) {
                    MMA_F16(acc[mi][ni], a, bh[ni]);
                    MMA_F16(acc[mi][ni], a, bl[ni]);
                }
            }
        }
        if (c + 1 < 5) { CP_WAIT0(); __syncthreads(); }
    }

    const int g  = lane >> 2;
    const int q2 = (lane & 3) * 2;
    #pragma unroll
    for (int mi = 0; mi < 2; mi++) {
        const int r0 = m0 + mw * 32 + mi * 16 + g;
        #pragma unroll
        for (int ni = 0; ni < 4; ni++) {
            const int cc = nb0 + nw * 32 + ni * 8 + q2;
            const float2 bv = *(const float2*)(bias + cc);
            #pragma unroll
            for (int h = 0; h < 2; h++) {
                const int r = r0 + h * 8;
                if (r < NN) {
                    const float2 b0 = *(const float2*)(base + (size_t)r * DD + cc);
                    float2 o;
                    o.x = b0.x + acc[mi][ni][2 * h + 0] + 2.f * bv.x;
                    o.y = b0.y + acc[mi][ni][2 * h + 1] + 2.f * bv.y;
                    *(float2*)(out + (size_t)r * DD + cc) = o;
                    const __half2 h2 = __floats2half2_rn(o.x, o.y);
                    *(uint32_t*)(g_X16 + (size_t)r * DD + cc) = *(const uint32_t*)&h2;
                }
            }
        }
    }
}

// ---------------- 2b) fused mu+logvar GEMM (kld partials only) --------------------
__global__ __launch_bounds__(512, 1)
void gemm_kld(const float* __restrict__ base,
              const float* __restrict__ b2, const float* __restrict__ b3)
{
    extern __shared__ char smc[];
    const uint32_t sb = smem_u32(smc);

    const int tid  = threadIdx.x;
    const int lane = tid & 31;
    const int wid  = tid >> 5;
    const int mw   = wid >> 2;
    const int nw   = wid & 3;
    const int m0   = blockIdx.x * 128;
    const int nb0  = blockIdx.y * 128;

    auto load_chunk = [&](int c, int bsel) {
        const uint32_t s0 = sb + bsel * B_BUF;
        for (int i = tid; i < 1024; i += 512) {
            const int row = i >> 3, u = i & 7;
            const uint32_t so = row * RPAD + u * 16;
            CP16(s0 + B_OA + so, g_A16 + (size_t)(m0 + row) * KDIM + c * 64 + u * 8);
        }
        for (int i = tid; i < 1024; i += 512) {
            const int row = i >> 3, u = i & 7;
            const size_t go = (size_t)(nb0 + row) * KDIM + c * 64 + u * 8;
            const uint32_t so = row * RPAD + u * 16;
            CP16(s0 + B_O2H + so, g_B16h[1] + go);
            CP16(s0 + B_O2L + so, g_B16l[1] + go);
            CP16(s0 + B_O3H + so, g_B16h[2] + go);
            CP16(s0 + B_O3L + so, g_B16l[2] + go);
        }
        CP_COMMIT();
    };

    float acc2[2][4][4], acc3[2][4][4];
    #pragma unroll
    for (int i = 0; i < 2; i++)
        #pragma unroll
        for (int j = 0; j < 4; j++)
            #pragma unroll
            for (int f = 0; f < 4; f++) { acc2[i][j][f] = 0.f; acc3[i][j][f] = 0.f; }

    load_chunk(0, 0);
    CP_WAIT0();
    __syncthreads();

    const uint32_t a_rb = (mw * 32 + (lane & 15)) * RPAD + (lane >> 4) * 16;
    const uint32_t b_rb = (nw * 32 + (lane & 7)) * RPAD + ((lane >> 3) & 1) * 16;

    for (int c = 0; c < 5; c++) {
        if (c + 1 < 5) load_chunk(c + 1, (c + 1) & 1);
        const uint32_t bufs = sb + (c & 1) * B_BUF;

        #pragma unroll
        for (int s = 0; s < 4; s++) {
            uint32_t b2h[4][2], b2l[4][2], b3h[4][2], b3l[4][2];
            #pragma unroll
            for (int ni = 0; ni < 4; ni++) {
                const uint32_t bd = bufs + b_rb + ni * (8 * RPAD) + s * 32;
                LDSM_X2(b2h[ni], bd + B_O2H);
                LDSM_X2(b2l[ni], bd + B_O2L);
                LDSM_X2(b3h[ni], bd + B_O3H);
                LDSM_X2(b3l[ni], bd + B_O3L);
            }
            #pragma unroll
            for (int mi = 0; mi < 2; mi++) {
                uint32_t a[4];
                LDSM_X4(a, bufs + B_OA + a_rb + mi * (16 * RPAD) + s * 32);
                #pragma unroll
                for (int ni = 0; ni < 4; ni++) {
                    MMA_F16(acc2[mi][ni], a, b2h[ni]);
                    MMA_F16(acc2[mi][ni], a, b2l[ni]);
                    MMA_F16(acc3[mi][ni], a, b3h[ni]);
                    MMA_F16(acc3[mi][ni], a, b3l[ni]);
                }
            }
        }
        if (c + 1 < 5) { CP_WAIT0(); __syncthreads(); }
    }

    const int g  = lane >> 2;
    const int q2 = (lane & 3) * 2;
    float smu = 0.f, slv = 0.f;
    #pragma unroll
    for (int mi = 0; mi < 2; mi++) {
        const int r0 = m0 + mw * 32 + mi * 16 + g;
        #pragma unroll
        for (int ni = 0; ni < 4; ni++) {
            const int cc = nb0 + nw * 32 + ni * 8 + q2;
            const float2 v2 = *(const float2*)(b2 + cc);
            const float2 v3 = *(const float2*)(b3 + cc);
            #pragma unroll
            for (int h = 0; h < 2; h++) {
                const int r = r0 + h * 8;
                if (r < NN) {
                    const float2 b0 = *(const float2*)(base + (size_t)r * DD + cc);
                    const float xm0 = b0.x + acc2[mi][ni][2 * h + 0] + 2.f * v2.x;
                    const float xm1 = b0.y + acc2[mi][ni][2 * h + 1] + 2.f * v2.y;
                    const float xl0 = b0.x + acc3[mi][ni][2 * h + 0] + 2.f * v3.x;
                    const float xl1 = b0.y + acc3[mi][ni][2 * h + 1] + 2.f * v3.y;
                    const float tm0 = tanhf(xm0), tm1 = tanhf(xm1);
                    const float tl0 = tanhf(xl0), tl1 = tanhf(xl1);
                    smu -= tm0 * tm0 + tm1 * tm1;
                    slv += 2.f + 2.f * (tl0 + tl1) - expf(2.f * tl0) - expf(2.f * tl1);
                }
            }
        }
    }

    __syncthreads();
    float* red = (float*)smc;
    red[tid] = smu;
    red[512 + tid] = slv;
    __syncthreads();
    #pragma unroll
    for (int o = 256; o > 0; o >>= 1) {
        if (tid < o) { red[tid] += red[tid + o]; red[512 + tid] += red[512 + tid + o]; }
        __syncthreads();
    }
    if (tid == 0)
        g_partials[blockIdx.y * gridDim.x + blockIdx.x] = red[0] + red[512];
}

// ---------------- 3) final kld reduction ------------------------------------------
__global__ void kld_final(int nslots, float* __restrict__ out_kld)
{
    if (threadIdx.x == 0 && blockIdx.x == 0) {
        double s = 0.0;
        for (int i = 0; i < nslots; i++) s += (double)g_partials[i];
        out_kld[0] = (float)(-0.5 * s / ((double)NN * (double)NN));
    }
}

// ---------------- launch ------------------------------------------------------------
extern "C" void kernel_launch(void* const* d_in, const int* in_sizes, int n_in,
                              void* d_out, int out_size)
{
    const float* node_reps = (const float*)d_in[0];
    const int*   in_idx    = (const int*)  d_in[1];
    const int*   in_edg    = (const int*)  d_in[2];
    const float* in_msk    = (const float*)d_in[3];
    const int*   out_idx   = (const int*)  d_in[4];
    const int*   out_edg   = (const int*)  d_in[5];
    const float* out_msk   = (const float*)d_in[6];
    const float* E1 = (const float*)d_in[7];
    const float* W1 = (const float*)d_in[8];
    const float* b1 = (const float*)d_in[9];
    const float* E2 = (const float*)d_in[10];
    const float* W2 = (const float*)d_in[11];
    const float* b2 = (const float*)d_in[12];
    const float* E3 = (const float*)d_in[13];
    const float* W3 = (const float*)d_in[14];
    const float* b3 = (const float*)d_in[15];

    float* hidden = (float*)d_out;

    cudaFuncSetAttribute(gemm_h,   cudaFuncAttributeMaxDynamicSharedMemorySize, SMEM_A);
    cudaFuncSetAttribute(gemm_kld, cudaFuncAttributeMaxDynamicSharedMemorySize, SMEM_B);

    const dim3 gg(MT, 2);

    prep_all<<<PB_CONV + PB_WB + PB_C, 256>>>(node_reps, W1, E1, W2, E2, W3, E3,
                                              in_edg, in_msk, out_edg, out_msk);

    gather16<<<(NN + 7) / 8, 256>>>(in_idx, in_msk, out_idx, out_msk);
    gemm_h<<<gg, 512, SMEM_A>>>(node_reps, b1, hidden);

    gather16<<<(NN + 7) / 8, 256>>>(in_idx, in_msk, out_idx, out_msk);
    gemm_kld<<<gg, 512, SMEM_B>>>(hidden, b2, b3);

    if (out_size > NN * DD)
        kld_final<<<1, 32>>>(2 * MT, hidden + (size_t)NN * DD);
}

// round 7
// speedup vs baseline: 3.0170x; 1.1997x over previous
#include <cuda_runtime.h>
#include <cuda_fp16.h>
#include <math.h>
#include <stdint.h>

#define NN    20000
#define KK    16
#define DD    256
#define VV    64
#define KDIM  320
#define MT    157
#define MROWS (MT * 128)

#define RPAD 144                  // smem row stride bytes (72 fp16)

// gemm_h smem (per buffer): A(128 rows) + B1h(64) + B1l(64)
#define A_OA  0
#define A_OBH 18432
#define A_OBL 27648
#define A_BUF 36864
#define SMEM_A (2 * A_BUF)        // 73728 -> 3 CTAs/SM
// gemm_kld smem: A + B2h + B2l + B3h + B3l (64 N-rows each)
#define B_OA  0
#define B_O2H 18432
#define B_O2L 27648
#define B_O3H 36864
#define B_O3L 46080
#define B_BUF 55296
#define SMEM_B (2 * B_BUF)        // 110592 -> 2 CTAs/SM

// prologue grid partition
#define PB_CONV 5000              // NN*DD/4 / 256
#define PB_WB   960               // 320 x 3
#define PB_C    2500              // NN / 8

// ---------------- scratch -------------------------------------------------------
__device__ __align__(16) __half g_A16[MROWS * KDIM];        // fp16 A (gather + C cols)
__device__ __align__(16) __half g_B16h[3][DD * KDIM];       // B transposed [n][k], hi
__device__ __align__(16) __half g_B16l[3][DD * KDIM];       // lo
__device__ __align__(16) __half g_X16[NN * DD];             // fp16 gather source
__device__ float g_partials[1024];

// ---------------- helpers -------------------------------------------------------
__device__ __forceinline__ uint32_t smem_u32(const void* p) {
    uint32_t a;
    asm("{ .reg .u64 t; cvta.to.shared.u64 t, %1; cvt.u32.u64 %0, t; }" : "=r"(a) : "l"(p));
    return a;
}
__device__ __forceinline__ void split1h(float x, __half& h, __half& l) {
    h = __float2half_rn(x);
    l = __float2half_rn(x - __half2float(h));
}
#define CP16(sa, ga) asm volatile("cp.async.ca.shared.global [%0], [%1], 16;" :: "r"(sa), "l"(ga))
#define CP_COMMIT()  asm volatile("cp.async.commit_group;" ::: "memory")
#define CP_WAIT0()   asm volatile("cp.async.wait_group 0;" ::: "memory")
#define LDSM_X4(r, a) \
    asm volatile("ldmatrix.sync.aligned.m8n8.x4.shared.b16 {%0,%1,%2,%3}, [%4];" \
        : "=r"((r)[0]), "=r"((r)[1]), "=r"((r)[2]), "=r"((r)[3]) : "r"(a))
#define LDSM_X2(r, a) \
    asm volatile("ldmatrix.sync.aligned.m8n8.x2.shared.b16 {%0,%1}, [%2];" \
        : "=r"((r)[0]), "=r"((r)[1]) : "r"(a))
#define MMA_F16(d, a, b) \
    asm volatile("mma.sync.aligned.m16n8k16.row.col.f32.f16.f16.f32 " \
        "{%0,%1,%2,%3}, {%4,%5,%6,%7}, {%8,%9}, {%0,%1,%2,%3};" \
        : "+f"((d)[0]), "+f"((d)[1]), "+f"((d)[2]), "+f"((d)[3]) \
        : "r"((a)[0]), "r"((a)[1]), "r"((a)[2]), "r"((a)[3]), "r"((b)[0]), "r"((b)[1]))

// ---------------- 0) fused prologue: conv16 | prep_wb | compute_c ----------------
__global__ void prep_all(const float* __restrict__ src,
                         const float* __restrict__ W1, const float* __restrict__ E1,
                         const float* __restrict__ W2, const float* __restrict__ E2,
                         const float* __restrict__ W3, const float* __restrict__ E3,
                         const int* __restrict__ ie, const float* __restrict__ im,
                         const int* __restrict__ oe, const float* __restrict__ om)
{
    const int b = blockIdx.x;
    const int tid = threadIdx.x;

    if (b < PB_CONV) {
        const int i = b * 256 + tid;
        const float4 v = ((const float4*)src)[i];
        const __half2 a2 = __floats2half2_rn(v.x, v.y);
        const __half2 b2 = __floats2half2_rn(v.z, v.w);
        uint2 u; u.x = *(const uint32_t*)&a2; u.y = *(const uint32_t*)&b2;
        ((uint2*)g_X16)[i] = u;
        return;
    }
    if (b < PB_CONV + PB_WB) {
        const int rb = b - PB_CONV;
        const int r = rb % KDIM;
        const int l = rb / KDIM;
        const int d = tid;
        const float* W = (l == 0) ? W1 : (l == 1) ? W2 : W3;
        const float* E = (l == 0) ? E1 : (l == 1) ? E2 : E3;
        float x;
        if (r < DD) {
            x = W[r * DD + d];
        } else {
            const int v = r - DD;
            __shared__ float sE[DD];
            sE[d] = E[v * DD + d];
            __syncthreads();
            float acc = 0.f;
            #pragma unroll 8
            for (int j = 0; j < DD; j++) acc += sE[j] * W[(DD + j) * DD + d];
            x = acc;
        }
        __half h, lo; split1h(x, h, lo);
        g_B16h[l][d * KDIM + r] = h;
        g_B16l[l][d * KDIM + r] = lo;
        return;
    }
    const int warp = tid >> 5;
    const int lane = tid & 31;
    const int n = (b - PB_CONV - PB_WB) * 8 + warp;
    if (n >= NN) return;

    int e; float m;
    if (lane < KK) { e = ie[n * KK + lane];      m = im[n * KK + lane]; }
    else           { e = oe[n * KK + lane - KK]; m = om[n * KK + lane - KK]; }

    float c0 = 0.f, c1 = 0.f;
    #pragma unroll
    for (int s = 0; s < 32; s++) {
        const int   ev = __shfl_sync(0xFFFFFFFFu, e, s);
        const float mv = __shfl_sync(0xFFFFFFFFu, m, s);
        if (ev == lane)      c0 += mv;
        if (ev == lane + 32) c1 += mv;
    }
    g_A16[n * KDIM + DD + lane]      = __float2half_rn(c0);
    g_A16[n * KDIM + DD + 32 + lane] = __float2half_rn(c1);
}

// ---------------- 1) fp16 gather-sum -> fp16 A -----------------------------------
__global__ void gather16(const int*   __restrict__ ii, const float* __restrict__ imk,
                         const int*   __restrict__ oi, const float* __restrict__ omk)
{
    const int warp = threadIdx.x >> 5;
    const int lane = threadIdx.x & 31;
    const int n = blockIdx.x * 8 + warp;
    if (n >= NN) return;

    int e; float m;
    if (lane < KK) { e = ii[n * KK + lane];      m = imk[n * KK + lane]; }
    else           { e = oi[n * KK + lane - KK]; m = omk[n * KK + lane - KK]; }

    float acc[8];
    #pragma unroll
    for (int j = 0; j < 8; j++) acc[j] = 0.f;

    #pragma unroll 8
    for (int k = 0; k < 32; k++) {
        const int   id = __shfl_sync(0xFFFFFFFFu, e, k);
        const float mm = __shfl_sync(0xFFFFFFFFu, m, k);
        const uint4 v = *(const uint4*)(g_X16 + (size_t)id * DD + lane * 8);
        const __half2* hp = (const __half2*)&v;
        #pragma unroll
        for (int j = 0; j < 4; j++) {
            const float2 f = __half22float2(hp[j]);
            acc[2 * j]     += mm * f.x;
            acc[2 * j + 1] += mm * f.y;
        }
    }
    __half hb[8];
    #pragma unroll
    for (int j = 0; j < 8; j++) hb[j] = __float2half_rn(acc[j]);
    *(uint4*)(g_A16 + (size_t)n * KDIM + lane * 8) = *(const uint4*)hb;
}

// ---------------- 2a) GEMM hidden: CTA 128x64, 8 warps, 3 CTAs/SM -----------------
__global__ __launch_bounds__(256)
void gemm_h(const float* __restrict__ base,
            const float* __restrict__ bias,
            float* __restrict__ out)
{
    extern __shared__ char smc[];
    const uint32_t sb = smem_u32(smc);

    const int tid  = threadIdx.x;
    const int lane = tid & 31;
    const int wid  = tid >> 5;
    const int mw   = wid >> 1;          // 0..3
    const int nw   = wid & 1;           // 0..1
    const int m0   = blockIdx.x * 128;
    const int nb0  = blockIdx.y * 64;

    const __half* __restrict__ Bh = g_B16h[0];
    const __half* __restrict__ Bl = g_B16l[0];

    auto load_chunk = [&](int c, int bsel) {
        const uint32_t s0 = sb + bsel * A_BUF;
        #pragma unroll
        for (int it = 0; it < 4; it++) {
            const int i = tid + it * 256;
            const int row = i >> 3, u = i & 7;
            CP16(s0 + A_OA + row * RPAD + u * 16,
                 g_A16 + (size_t)(m0 + row) * KDIM + c * 64 + u * 8);
        }
        #pragma unroll
        for (int it = 0; it < 2; it++) {
            const int i = tid + it * 256;
            const int row = i >> 3, u = i & 7;
            const size_t go = (size_t)(nb0 + row) * KDIM + c * 64 + u * 8;
            const uint32_t so = row * RPAD + u * 16;
            CP16(s0 + A_OBH + so, Bh + go);
            CP16(s0 + A_OBL + so, Bl + go);
        }
        CP_COMMIT();
    };

    float acc[2][4][4];
    #pragma unroll
    for (int i = 0; i < 2; i++)
        #pragma unroll
        for (int j = 0; j < 4; j++)
            #pragma unroll
            for (int f = 0; f < 4; f++) acc[i][j][f] = 0.f;

    load_chunk(0, 0);
    CP_WAIT0();
    __syncthreads();

    const uint32_t a_rb = (mw * 32 + (lane & 15)) * RPAD + (lane >> 4) * 16;
    const uint32_t b_rb = (nw * 32 + (lane & 7)) * RPAD + ((lane >> 3) & 1) * 16;

    for (int c = 0; c < 5; c++) {
        if (c + 1 < 5) load_chunk(c + 1, (c + 1) & 1);
        const uint32_t bufs = sb + (c & 1) * A_BUF;

        #pragma unroll
        for (int s = 0; s < 4; s++) {
            uint32_t bh[4][2], bl[4][2];
            #pragma unroll
            for (int ni = 0; ni < 4; ni++) {
                const uint32_t bd = bufs + b_rb + ni * (8 * RPAD) + s * 32;
                LDSM_X2(bh[ni], bd + A_OBH);
                LDSM_X2(bl[ni], bd + A_OBL);
            }
            #pragma unroll
            for (int mi = 0; mi < 2; mi++) {
                uint32_t a[4];
                LDSM_X4(a, bufs + A_OA + a_rb + mi * (16 * RPAD) + s * 32);
                #pragma unroll
                for (int ni = 0; ni < 4; ni++) {
                    MMA_F16(acc[mi][ni], a, bh[ni]);
                    MMA_F16(acc[mi][ni], a, bl[ni]);
                }
            }
        }
        if (c + 1 < 5) { CP_WAIT0(); __syncthreads(); }
    }

    const int g  = lane >> 2;
    const int q2 = (lane & 3) * 2;
    #pragma unroll
    for (int mi = 0; mi < 2; mi++) {
        const int r0 = m0 + mw * 32 + mi * 16 + g;
        #pragma unroll
        for (int ni = 0; ni < 4; ni++) {
            const int cc = nb0 + nw * 32 + ni * 8 + q2;
            const float2 bv = *(const float2*)(bias + cc);
            #pragma unroll
            for (int h = 0; h < 2; h++) {
                const int r = r0 + h * 8;
                if (r < NN) {
                    const float2 b0 = *(const float2*)(base + (size_t)r * DD + cc);
                    float2 o;
                    o.x = b0.x + acc[mi][ni][2 * h + 0] + 2.f * bv.x;
                    o.y = b0.y + acc[mi][ni][2 * h + 1] + 2.f * bv.y;
                    *(float2*)(out + (size_t)r * DD + cc) = o;
                    const __half2 h2 = __floats2half2_rn(o.x, o.y);
                    *(uint32_t*)(g_X16 + (size_t)r * DD + cc) = *(const uint32_t*)&h2;
                }
            }
        }
    }
}

// ---------------- 2b) fused mu+logvar GEMM: CTA 128x64, 2 CTAs/SM -----------------
__global__ __launch_bounds__(256)
void gemm_kld(const float* __restrict__ base,
              const float* __restrict__ b2, const float* __restrict__ b3)
{
    extern __shared__ char smc[];
    const uint32_t sb = smem_u32(smc);

    const int tid  = threadIdx.x;
    const int lane = tid & 31;
    const int wid  = tid >> 5;
    const int mw   = wid >> 1;
    const int nw   = wid & 1;
    const int m0   = blockIdx.x * 128;
    const int nb0  = blockIdx.y * 64;

    auto load_chunk = [&](int c, int bsel) {
        const uint32_t s0 = sb + bsel * B_BUF;
        #pragma unroll
        for (int it = 0; it < 4; it++) {
            const int i = tid + it * 256;
            const int row = i >> 3, u = i & 7;
            CP16(s0 + B_OA + row * RPAD + u * 16,
                 g_A16 + (size_t)(m0 + row) * KDIM + c * 64 + u * 8);
        }
        #pragma unroll
        for (int it = 0; it < 2; it++) {
            const int i = tid + it * 256;
            const int row = i >> 3, u = i & 7;
            const size_t go = (size_t)(nb0 + row) * KDIM + c * 64 + u * 8;
            const uint32_t so = row * RPAD + u * 16;
            CP16(s0 + B_O2H + so, g_B16h[1] + go);
            CP16(s0 + B_O2L + so, g_B16l[1] + go);
            CP16(s0 + B_O3H + so, g_B16h[2] + go);
            CP16(s0 + B_O3L + so, g_B16l[2] + go);
        }
        CP_COMMIT();
    };

    float acc2[2][4][4], acc3[2][4][4];
    #pragma unroll
    for (int i = 0; i < 2; i++)
        #pragma unroll
        for (int j = 0; j < 4; j++)
            #pragma unroll
            for (int f = 0; f < 4; f++) { acc2[i][j][f] = 0.f; acc3[i][j][f] = 0.f; }

    load_chunk(0, 0);
    CP_WAIT0();
    __syncthreads();

    const uint32_t a_rb = (mw * 32 + (lane & 15)) * RPAD + (lane >> 4) * 16;
    const uint32_t b_rb = (nw * 32 + (lane & 7)) * RPAD + ((lane >> 3) & 1) * 16;

    for (int c = 0; c < 5; c++) {
        if (c + 1 < 5) load_chunk(c + 1, (c + 1) & 1);
        const uint32_t bufs = sb + (c & 1) * B_BUF;

        #pragma unroll
        for (int s = 0; s < 4; s++) {
            uint32_t b2h[4][2], b2l[4][2], b3h[4][2], b3l[4][2];
            #pragma unroll
            for (int ni = 0; ni < 4; ni++) {
                const uint32_t bd = bufs + b_rb + ni * (8 * RPAD) + s * 32;
                LDSM_X2(b2h[ni], bd + B_O2H);
                LDSM_X2(b2l[ni], bd + B_O2L);
                LDSM_X2(b3h[ni], bd + B_O3H);
                LDSM_X2(b3l[ni], bd + B_O3L);
            }
            #pragma unroll
            for (int mi = 0; mi < 2; mi++) {
                uint32_t a[4];
                LDSM_X4(a, bufs + B_OA + a_rb + mi * (16 * RPAD) + s * 32);
                #pragma unroll
                for (int ni = 0; ni < 4; ni++) {
                    MMA_F16(acc2[mi][ni], a, b2h[ni]);
                    MMA_F16(acc2[mi][ni], a, b2l[ni]);
                    MMA_F16(acc3[mi][ni], a, b3h[ni]);
                    MMA_F16(acc3[mi][ni], a, b3l[ni]);
                }
            }
        }
        if (c + 1 < 5) { CP_WAIT0(); __syncthreads(); }
    }

    const int g  = lane >> 2;
    const int q2 = (lane & 3) * 2;
    float smu = 0.f, slv = 0.f;
    #pragma unroll
    for (int mi = 0; mi < 2; mi++) {
        const int r0 = m0 + mw * 32 + mi * 16 + g;
        #pragma unroll
        for (int ni = 0; ni < 4; ni++) {
            const int cc = nb0 + nw * 32 + ni * 8 + q2;
            const float2 v2 = *(const float2*)(b2 + cc);
            const float2 v3 = *(const float2*)(b3 + cc);
            #pragma unroll
            for (int h = 0; h < 2; h++) {
                const int r = r0 + h * 8;
                if (r < NN) {
                    const float2 b0 = *(const float2*)(base + (size_t)r * DD + cc);
                    const float xm0 = b0.x + acc2[mi][ni][2 * h + 0] + 2.f * v2.x;
                    const float xm1 = b0.y + acc2[mi][ni][2 * h + 1] + 2.f * v2.y;
                    const float xl0 = b0.x + acc3[mi][ni][2 * h + 0] + 2.f * v3.x;
                    const float xl1 = b0.y + acc3[mi][ni][2 * h + 1] + 2.f * v3.y;
                    const float tm0 = tanhf(xm0), tm1 = tanhf(xm1);
                    const float tl0 = tanhf(xl0), tl1 = tanhf(xl1);
                    smu -= tm0 * tm0 + tm1 * tm1;
                    slv += 2.f + 2.f * (tl0 + tl1) - expf(2.f * tl0) - expf(2.f * tl1);
                }
            }
        }
    }

    __syncthreads();
    float* red = (float*)smc;
    red[tid] = smu;
    red[256 + tid] = slv;
    __syncthreads();
    #pragma unroll
    for (int o = 128; o > 0; o >>= 1) {
        if (tid < o) { red[tid] += red[tid + o]; red[256 + tid] += red[256 + tid + o]; }
        __syncthreads();
    }
    if (tid == 0)
        g_partials[blockIdx.y * gridDim.x + blockIdx.x] = red[0] + red[256];
}

// ---------------- 3) final kld reduction (parallel, pow2-safe) --------------------
__global__ void kld_final(int nslots, float* __restrict__ out_kld)
{
    __shared__ double red[512];
    const int t = threadIdx.x;
    double s = 0.0;
    for (int i = t; i < nslots; i += 512) s += (double)g_partials[i];
    red[t] = s;
    __syncthreads();
    #pragma unroll
    for (int o = 256; o > 0; o >>= 1) {
        if (t < o) red[t] += red[t + o];
        __syncthreads();
    }
    if (t == 0)
        out_kld[0] = (float)(-0.5 * red[0] / ((double)NN * (double)NN));
}

// ---------------- launch ------------------------------------------------------------
extern "C" void kernel_launch(void* const* d_in, const int* in_sizes, int n_in,
                              void* d_out, int out_size)
{
    const float* node_reps = (const float*)d_in[0];
    const int*   in_idx    = (const int*)  d_in[1];
    const int*   in_edg    = (const int*)  d_in[2];
    const float* in_msk    = (const float*)d_in[3];
    const int*   out_idx   = (const int*)  d_in[4];
    const int*   out_edg   = (const int*)  d_in[5];
    const float* out_msk   = (const float*)d_in[6];
    const float* E1 = (const float*)d_in[7];
    const float* W1 = (const float*)d_in[8];
    const float* b1 = (const float*)d_in[9];
    const float* E2 = (const float*)d_in[10];
    const float* W2 = (const float*)d_in[11];
    const float* b2 = (const float*)d_in[12];
    const float* E3 = (const float*)d_in[13];
    const float* W3 = (const float*)d_in[14];
    const float* b3 = (const float*)d_in[15];

    float* hidden = (float*)d_out;

    cudaFuncSetAttribute(gemm_h,   cudaFuncAttributeMaxDynamicSharedMemorySize, SMEM_A);
    cudaFuncSetAttribute(gemm_kld, cudaFuncAttributeMaxDynamicSharedMemorySize, SMEM_B);

    const dim3 gg(MT, 4);   // 628 CTAs, N tile 64

    prep_all<<<PB_CONV + PB_WB + PB_C, 256>>>(node_reps, W1, E1, W2, E2, W3, E3,
                                              in_edg, in_msk, out_edg, out_msk);

    gather16<<<(NN + 7) / 8, 256>>>(in_idx, in_msk, out_idx, out_msk);
    gemm_h<<<gg, 256, SMEM_A>>>(node_reps, b1, hidden);

    gather16<<<(NN + 7) / 8, 256>>>(in_idx, in_msk, out_idx, out_msk);
    gemm_kld<<<gg, 256, SMEM_B>>>(hidden, b2, b3);

    if (out_size > NN * DD)
        kld_final<<<1, 512>>>(4 * MT, hidden + (size_t)NN * DD);
}

// round 8
// speedup vs baseline: 3.6573x; 1.2122x over previous
#include <cuda_runtime.h>
#include <cuda_fp16.h>
#include <math.h>
#include <stdint.h>

#define NN    20000
#define KK    16
#define DD    256
#define VV    64
#define KDIM  320
#define MT    157
#define MROWS (MT * 128)

#define RPAD 144                  // smem row stride bytes (72 fp16)

// gemm_h smem (per buffer): A(128 rows) + B1(64 rows)
#define A_OA  0
#define A_OB  18432
#define A_BUF 27648
#define SMEM_A (2 * A_BUF)        // 55296
// gemm_kld smem: A + B2 + B3
#define B_OA  0
#define B_O2  18432
#define B_O3  27648
#define B_BUF 36864
#define SMEM_B (2 * B_BUF)        // 73728 -> 3 CTAs/SM

// prologue grid partition
#define PB_CONV 5000              // NN*DD/4 / 256
#define PB_WB   960               // 320 x 3
#define PB_C    2500              // NN / 8

// ---------------- scratch -------------------------------------------------------
__device__ __align__(16) __half g_A16[MROWS * KDIM];        // fp16 A (gather + C cols)
__device__ __align__(16) __half g_B16[3][DD * KDIM];        // B transposed [n][k], fp16
__device__ __align__(16) __half g_X16[NN * DD];             // fp16 gather source
__device__ float g_partials[1024];

// ---------------- helpers -------------------------------------------------------
__device__ __forceinline__ uint32_t smem_u32(const void* p) {
    uint32_t a;
    asm("{ .reg .u64 t; cvta.to.shared.u64 t, %1; cvt.u32.u64 %0, t; }" : "=r"(a) : "l"(p));
    return a;
}
__device__ __forceinline__ uint64_t pack_f2(float x, float y) {
    uint64_t r;
    asm("mov.b64 %0, {%1, %2};" : "=l"(r) : "f"(x), "f"(y));
    return r;
}
__device__ __forceinline__ void unpack_f2(uint64_t v, float& x, float& y) {
    asm("mov.b64 {%0, %1}, %2;" : "=f"(x), "=f"(y) : "l"(v));
}
__device__ __forceinline__ void fma_f32x2(uint64_t& d, uint64_t a, uint64_t b) {
    asm("fma.rn.f32x2 %0, %1, %2, %0;" : "+l"(d) : "l"(a), "l"(b));
}
#define CP16(sa, ga) asm volatile("cp.async.ca.shared.global [%0], [%1], 16;" :: "r"(sa), "l"(ga))
#define CP_COMMIT()  asm volatile("cp.async.commit_group;" ::: "memory")
#define CP_WAIT0()   asm volatile("cp.async.wait_group 0;" ::: "memory")
#define LDSM_X4(r, a) \
    asm volatile("ldmatrix.sync.aligned.m8n8.x4.shared.b16 {%0,%1,%2,%3}, [%4];" \
        : "=r"((r)[0]), "=r"((r)[1]), "=r"((r)[2]), "=r"((r)[3]) : "r"(a))
#define LDSM_X2(r, a) \
    asm volatile("ldmatrix.sync.aligned.m8n8.x2.shared.b16 {%0,%1}, [%2];" \
        : "=r"((r)[0]), "=r"((r)[1]) : "r"(a))
#define MMA_F16(d, a, b) \
    asm volatile("mma.sync.aligned.m16n8k16.row.col.f32.f16.f16.f32 " \
        "{%0,%1,%2,%3}, {%4,%5,%6,%7}, {%8,%9}, {%0,%1,%2,%3};" \
        : "+f"((d)[0]), "+f"((d)[1]), "+f"((d)[2]), "+f"((d)[3]) \
        : "r"((a)[0]), "r"((a)[1]), "r"((a)[2]), "r"((a)[3]), "r"((b)[0]), "r"((b)[1]))

// ---------------- 0) fused prologue: conv16 | prep_wb | compute_c ----------------
__global__ void prep_all(const float* __restrict__ src,
                         const float* __restrict__ W1, const float* __restrict__ E1,
                         const float* __restrict__ W2, const float* __restrict__ E2,
                         const float* __restrict__ W3, const float* __restrict__ E3,
                         const int* __restrict__ ie, const float* __restrict__ im,
                         const int* __restrict__ oe, const float* __restrict__ om)
{
    const int b = blockIdx.x;
    const int tid = threadIdx.x;

    if (b < PB_CONV) {
        const int i = b * 256 + tid;
        const float4 v = ((const float4*)src)[i];
        const __half2 a2 = __floats2half2_rn(v.x, v.y);
        const __half2 b2 = __floats2half2_rn(v.z, v.w);
        uint2 u; u.x = *(const uint32_t*)&a2; u.y = *(const uint32_t*)&b2;
        ((uint2*)g_X16)[i] = u;
        return;
    }
    if (b < PB_CONV + PB_WB) {
        const int rb = b - PB_CONV;
        const int r = rb % KDIM;
        const int l = rb / KDIM;
        const int d = tid;
        const float* W = (l == 0) ? W1 : (l == 1) ? W2 : W3;
        const float* E = (l == 0) ? E1 : (l == 1) ? E2 : E3;
        float x;
        if (r < DD) {
            x = W[r * DD + d];
        } else {
            const int v = r - DD;
            __shared__ float sE[DD];
            sE[d] = E[v * DD + d];
            __syncthreads();
            float acc = 0.f;
            #pragma unroll 8
            for (int j = 0; j < DD; j++) acc += sE[j] * W[(DD + j) * DD + d];
            x = acc;
        }
        g_B16[l][d * KDIM + r] = __float2half_rn(x);
        return;
    }
    const int warp = tid >> 5;
    const int lane = tid & 31;
    const int n = (b - PB_CONV - PB_WB) * 8 + warp;
    if (n >= NN) return;

    int e; float m;
    if (lane < KK) { e = ie[n * KK + lane];      m = im[n * KK + lane]; }
    else           { e = oe[n * KK + lane - KK]; m = om[n * KK + lane - KK]; }

    float c0 = 0.f, c1 = 0.f;
    #pragma unroll
    for (int s = 0; s < 32; s++) {
        const int   ev = __shfl_sync(0xFFFFFFFFu, e, s);
        const float mv = __shfl_sync(0xFFFFFFFFu, m, s);
        if (ev == lane)      c0 += mv;
        if (ev == lane + 32) c1 += mv;
    }
    g_A16[n * KDIM + DD + lane]      = __float2half_rn(c0);
    g_A16[n * KDIM + DD + 32 + lane] = __float2half_rn(c1);
}

// ---------------- 1) fp16 gather-sum (packed f32x2 accum) -> fp16 A --------------
__global__ void gather16(const int*   __restrict__ ii, const float* __restrict__ imk,
                         const int*   __restrict__ oi, const float* __restrict__ omk)
{
    const int warp = threadIdx.x >> 5;
    const int lane = threadIdx.x & 31;
    const int n = blockIdx.x * 8 + warp;
    if (n >= NN) return;

    int e; float m;
    if (lane < KK) { e = ii[n * KK + lane];      m = imk[n * KK + lane]; }
    else           { e = oi[n * KK + lane - KK]; m = omk[n * KK + lane - KK]; }

    uint64_t acc[4] = {0ull, 0ull, 0ull, 0ull};   // 4x packed f32x2

    #pragma unroll 8
    for (int k = 0; k < 32; k++) {
        const int   id = __shfl_sync(0xFFFFFFFFu, e, k);
        const float mm = __shfl_sync(0xFFFFFFFFu, m, k);
        const uint64_t m2 = pack_f2(mm, mm);
        const uint4 v = *(const uint4*)(g_X16 + (size_t)id * DD + lane * 8);
        const __half2* hp = (const __half2*)&v;
        #pragma unroll
        for (int j = 0; j < 4; j++) {
            const float2 f = __half22float2(hp[j]);
            fma_f32x2(acc[j], pack_f2(f.x, f.y), m2);
        }
    }
    __half hb[8];
    #pragma unroll
    for (int j = 0; j < 4; j++) {
        float x, y;
        unpack_f2(acc[j], x, y);
        hb[2 * j]     = __float2half_rn(x);
        hb[2 * j + 1] = __float2half_rn(y);
    }
    *(uint4*)(g_A16 + (size_t)n * KDIM + lane * 8) = *(const uint4*)hb;
}

// ---------------- 2a) GEMM hidden: CTA 128x64, single fp16 B ----------------------
__global__ __launch_bounds__(256, 3)
void gemm_h(const float* __restrict__ base,
            const float* __restrict__ bias,
            float* __restrict__ out)
{
    extern __shared__ char smc[];
    const uint32_t sb = smem_u32(smc);

    const int tid  = threadIdx.x;
    const int lane = tid & 31;
    const int wid  = tid >> 5;
    const int mw   = wid >> 1;          // 0..3
    const int nw   = wid & 1;           // 0..1
    const int m0   = blockIdx.x * 128;
    const int nb0  = blockIdx.y * 64;

    const __half* __restrict__ B1 = g_B16[0];

    auto load_chunk = [&](int c, int bsel) {
        const uint32_t s0 = sb + bsel * A_BUF;
        #pragma unroll
        for (int it = 0; it < 4; it++) {
            const int i = tid + it * 256;
            const int row = i >> 3, u = i & 7;
            CP16(s0 + A_OA + row * RPAD + u * 16,
                 g_A16 + (size_t)(m0 + row) * KDIM + c * 64 + u * 8);
        }
        #pragma unroll
        for (int it = 0; it < 2; it++) {
            const int i = tid + it * 256;
            const int row = i >> 3, u = i & 7;
            CP16(s0 + A_OB + row * RPAD + u * 16,
                 B1 + (size_t)(nb0 + row) * KDIM + c * 64 + u * 8);
        }
        CP_COMMIT();
    };

    float acc[2][4][4];
    #pragma unroll
    for (int i = 0; i < 2; i++)
        #pragma unroll
        for (int j = 0; j < 4; j++)
            #pragma unroll
            for (int f = 0; f < 4; f++) acc[i][j][f] = 0.f;

    load_chunk(0, 0);
    CP_WAIT0();
    __syncthreads();

    const uint32_t a_rb = (mw * 32 + (lane & 15)) * RPAD + (lane >> 4) * 16;
    const uint32_t b_rb = (nw * 32 + (lane & 7)) * RPAD + ((lane >> 3) & 1) * 16;

    for (int c = 0; c < 5; c++) {
        if (c + 1 < 5) load_chunk(c + 1, (c + 1) & 1);
        const uint32_t bufs = sb + (c & 1) * A_BUF;

        #pragma unroll
        for (int s = 0; s < 4; s++) {
            uint32_t bh[4][2];
            #pragma unroll
            for (int ni = 0; ni < 4; ni++)
                LDSM_X2(bh[ni], bufs + A_OB + b_rb + ni * (8 * RPAD) + s * 32);
            #pragma unroll
            for (int mi = 0; mi < 2; mi++) {
                uint32_t a[4];
                LDSM_X4(a, bufs + A_OA + a_rb + mi * (16 * RPAD) + s * 32);
                #pragma unroll
                for (int ni = 0; ni < 4; ni++)
                    MMA_F16(acc[mi][ni], a, bh[ni]);
            }
        }
        if (c + 1 < 5) { CP_WAIT0(); __syncthreads(); }
    }

    const int g  = lane >> 2;
    const int q2 = (lane & 3) * 2;
    #pragma unroll
    for (int mi = 0; mi < 2; mi++) {
        const int r0 = m0 + mw * 32 + mi * 16 + g;
        #pragma unroll
        for (int ni = 0; ni < 4; ni++) {
            const int cc = nb0 + nw * 32 + ni * 8 + q2;
            const float2 bv = *(const float2*)(bias + cc);
            #pragma unroll
            for (int h = 0; h < 2; h++) {
                const int r = r0 + h * 8;
                if (r < NN) {
                    const float2 b0 = *(const float2*)(base + (size_t)r * DD + cc);
                    float2 o;
                    o.x = b0.x + acc[mi][ni][2 * h + 0] + 2.f * bv.x;
                    o.y = b0.y + acc[mi][ni][2 * h + 1] + 2.f * bv.y;
                    *(float2*)(out + (size_t)r * DD + cc) = o;
                    const __half2 h2 = __floats2half2_rn(o.x, o.y);
                    *(uint32_t*)(g_X16 + (size_t)r * DD + cc) = *(const uint32_t*)&h2;
                }
            }
        }
    }
}

// ---------------- 2b) fused mu+logvar GEMM: single fp16 B, 3 CTAs/SM --------------
__global__ __launch_bounds__(256)
void gemm_kld(const float* __restrict__ base,
              const float* __restrict__ b2, const float* __restrict__ b3)
{
    extern __shared__ char smc[];
    const uint32_t sb = smem_u32(smc);

    const int tid  = threadIdx.x;
    const int lane = tid & 31;
    const int wid  = tid >> 5;
    const int mw   = wid >> 1;
    const int nw   = wid & 1;
    const int m0   = blockIdx.x * 128;
    const int nb0  = blockIdx.y * 64;

    auto load_chunk = [&](int c, int bsel) {
        const uint32_t s0 = sb + bsel * B_BUF;
        #pragma unroll
        for (int it = 0; it < 4; it++) {
            const int i = tid + it * 256;
            const int row = i >> 3, u = i & 7;
            CP16(s0 + B_OA + row * RPAD + u * 16,
                 g_A16 + (size_t)(m0 + row) * KDIM + c * 64 + u * 8);
        }
        #pragma unroll
        for (int it = 0; it < 2; it++) {
            const int i = tid + it * 256;
            const int row = i >> 3, u = i & 7;
            const size_t go = (size_t)(nb0 + row) * KDIM + c * 64 + u * 8;
            const uint32_t so = row * RPAD + u * 16;
            CP16(s0 + B_O2 + so, g_B16[1] + go);
            CP16(s0 + B_O3 + so, g_B16[2] + go);
        }
        CP_COMMIT();
    };

    float acc2[2][4][4], acc3[2][4][4];
    #pragma unroll
    for (int i = 0; i < 2; i++)
        #pragma unroll
        for (int j = 0; j < 4; j++)
            #pragma unroll
            for (int f = 0; f < 4; f++) { acc2[i][j][f] = 0.f; acc3[i][j][f] = 0.f; }

    load_chunk(0, 0);
    CP_WAIT0();
    __syncthreads();

    const uint32_t a_rb = (mw * 32 + (lane & 15)) * RPAD + (lane >> 4) * 16;
    const uint32_t b_rb = (nw * 32 + (lane & 7)) * RPAD + ((lane >> 3) & 1) * 16;

    for (int c = 0; c < 5; c++) {
        if (c + 1 < 5) load_chunk(c + 1, (c + 1) & 1);
        const uint32_t bufs = sb + (c & 1) * B_BUF;

        #pragma unroll
        for (int s = 0; s < 4; s++) {
            uint32_t v2[4][2], v3[4][2];
            #pragma unroll
            for (int ni = 0; ni < 4; ni++) {
                const uint32_t bd = bufs + b_rb + ni * (8 * RPAD) + s * 32;
                LDSM_X2(v2[ni], bd + B_O2);
                LDSM_X2(v3[ni], bd + B_O3);
            }
            #pragma unroll
            for (int mi = 0; mi < 2; mi++) {
                uint32_t a[4];
                LDSM_X4(a, bufs + B_OA + a_rb + mi * (16 * RPAD) + s * 32);
                #pragma unroll
                for (int ni = 0; ni < 4; ni++) {
                    MMA_F16(acc2[mi][ni], a, v2[ni]);
                    MMA_F16(acc3[mi][ni], a, v3[ni]);
                }
            }
        }
        if (c + 1 < 5) { CP_WAIT0(); __syncthreads(); }
    }

    const int g  = lane >> 2;
    const int q2 = (lane & 3) * 2;
    float smu = 0.f, slv = 0.f;
    #pragma unroll
    for (int mi = 0; mi < 2; mi++) {
        const int r0 = m0 + mw * 32 + mi * 16 + g;
        #pragma unroll
        for (int ni = 0; ni < 4; ni++) {
            const int cc = nb0 + nw * 32 + ni * 8 + q2;
            const float2 w2 = *(const float2*)(b2 + cc);
            const float2 w3 = *(const float2*)(b3 + cc);
            #pragma unroll
            for (int h = 0; h < 2; h++) {
                const int r = r0 + h * 8;
                if (r < NN) {
                    const float2 b0 = *(const float2*)(base + (size_t)r * DD + cc);
                    const float xm0 = b0.x + acc2[mi][ni][2 * h + 0] + 2.f * w2.x;
                    const float xm1 = b0.y + acc2[mi][ni][2 * h + 1] + 2.f * w2.y;
                    const float xl0 = b0.x + acc3[mi][ni][2 * h + 0] + 2.f * w3.x;
                    const float xl1 = b0.y + acc3[mi][ni][2 * h + 1] + 2.f * w3.y;
                    const float tm0 = tanhf(xm0), tm1 = tanhf(xm1);
                    const float tl0 = tanhf(xl0), tl1 = tanhf(xl1);
                    smu -= tm0 * tm0 + tm1 * tm1;
                    slv += 2.f + 2.f * (tl0 + tl1) - expf(2.f * tl0) - expf(2.f * tl1);
                }
            }
        }
    }

    __syncthreads();
    float* red = (float*)smc;
    red[tid] = smu;
    red[256 + tid] = slv;
    __syncthreads();
    #pragma unroll
    for (int o = 128; o > 0; o >>= 1) {
        if (tid < o) { red[tid] += red[tid + o]; red[256 + tid] += red[256 + tid + o]; }
        __syncthreads();
    }
    if (tid == 0)
        g_partials[blockIdx.y * gridDim.x + blockIdx.x] = red[0] + red[256];
}

// ---------------- 3) final kld reduction (parallel, pow2-safe) --------------------
__global__ void kld_final(int nslots, float* __restrict__ out_kld)
{
    __shared__ double red[512];
    const int t = threadIdx.x;
    double s = 0.0;
    for (int i = t; i < nslots; i += 512) s += (double)g_partials[i];
    red[t] = s;
    __syncthreads();
    #pragma unroll
    for (int o = 256; o > 0; o >>= 1) {
        if (t < o) red[t] += red[t + o];
        __syncthreads();
    }
    if (t == 0)
        out_kld[0] = (float)(-0.5 * red[0] / ((double)NN * (double)NN));
}

// ---------------- launch ------------------------------------------------------------
extern "C" void kernel_launch(void* const* d_in, const int* in_sizes, int n_in,
                              void* d_out, int out_size)
{
    const float* node_reps = (const float*)d_in[0];
    const int*   in_idx    = (const int*)  d_in[1];
    const int*   in_edg    = (const int*)  d_in[2];
    const float* in_msk    = (const float*)d_in[3];
    const int*   out_idx   = (const int*)  d_in[4];
    const int*   out_edg   = (const int*)  d_in[5];
    const float* out_msk   = (const float*)d_in[6];
    const float* E1 = (const float*)d_in[7];
    const float* W1 = (const float*)d_in[8];
    const float* b1 = (const float*)d_in[9];
    const float* E2 = (const float*)d_in[10];
    const float* W2 = (const float*)d_in[11];
    const float* b2 = (const float*)d_in[12];
    const float* E3 = (const float*)d_in[13];
    const float* W3 = (const float*)d_in[14];
    const float* b3 = (const float*)d_in[15];

    float* hidden = (float*)d_out;

    cudaFuncSetAttribute(gemm_h,   cudaFuncAttributeMaxDynamicSharedMemorySize, SMEM_A);
    cudaFuncSetAttribute(gemm_kld, cudaFuncAttributeMaxDynamicSharedMemorySize, SMEM_B);

    const dim3 gg(MT, 4);   // 628 CTAs, N tile 64

    prep_all<<<PB_CONV + PB_WB + PB_C, 256>>>(node_reps, W1, E1, W2, E2, W3, E3,
                                              in_edg, in_msk, out_edg, out_msk);

    gather16<<<(NN + 7) / 8, 256>>>(in_idx, in_msk, out_idx, out_msk);
    gemm_h<<<gg, 256, SMEM_A>>>(node_reps, b1, hidden);

    gather16<<<(NN + 7) / 8, 256>>>(in_idx, in_msk, out_idx, out_msk);
    gemm_kld<<<gg, 256, SMEM_B>>>(hidden, b2, b3);

    if (out_size > NN * DD)
        kld_final<<<1, 512>>>(4 * MT, hidden + (size_t)NN * DD);
}